// round 4
// baseline (speedup 1.0000x reference)
#include <cuda_runtime.h>

// ---------------------------------------------------------------------------
// HyperAttention, GB300 round 1: fused block-diagonal + sampled-residual
// attention (joint softmax), fp32 with packed f32x2 FFMA.
//
// Shapes (fixed by the problem): B=2, H=16, N=8192, D=64, 7 projections,
// BLOCK=256, SAMPLE=256 -> per (b,h): 32 query blocks x (256 block keys +
// 256 sampled keys).
// ---------------------------------------------------------------------------

#define BH      32          // B*H
#define NSEQ    8192
#define DIM     64
#define NPROJ   7
#define NBUCK   128         // 2^NPROJ
#define NSEG    128
#define SEGLEN  64          // NSEG*SEGLEN == NSEQ
#define ST      130         // padded segment-hist stride (uint16) -> conflict-free
#define LOG32   3.4657359027997265f
#define BIGNEG  (-1e30f)

typedef unsigned long long ull;

// scratch (device globals; no allocations allowed)
__device__ unsigned char g_hash[2][BH * NSEQ];
__device__ int           g_idx[2][BH * NSEQ];   // [0]=q_idx, [1]=k_idx

// ---- packed fp32x2 helpers (sm_100+ PTX) ----------------------------------
__device__ __forceinline__ ull pk2(float a, float b) {
    ull r; asm("mov.b64 %0, {%1, %2};" : "=l"(r) : "f"(a), "f"(b)); return r;
}
__device__ __forceinline__ void upk2(ull x, float& a, float& b) {
    asm("mov.b64 {%0, %1}, %2;" : "=f"(a), "=f"(b) : "l"(x));
}
__device__ __forceinline__ ull f2fma(ull a, ull b, ull c) {
    ull d; asm("fma.rn.f32x2 %0, %1, %2, %3;" : "=l"(d) : "l"(a), "l"(b), "l"(c));
    return d;
}
__device__ __forceinline__ ull f2mul(ull a, ull b) {
    ull d; asm("mul.rn.f32x2 %0, %1, %2;" : "=l"(d) : "l"(a), "l"(b));
    return d;
}

// ---------------------------------------------------------------------------
// Kernel 1: angular LSH hash.  One warp per row (cooperative dot products).
// hash = gray(code), gray(c) = c ^ (c>>1)   (== PERM lookup in the reference)
// ---------------------------------------------------------------------------
__global__ void hash_kernel(const float* __restrict__ x,
                            const float* __restrict__ proj, int which) {
    unsigned char* out = g_hash[which];
    const int lane = threadIdx.x & 31;
    const int gw   = (blockIdx.x * blockDim.x + threadIdx.x) >> 5;
    const int nw   = (gridDim.x * blockDim.x) >> 5;

    float pj0[NPROJ], pj1[NPROJ];
#pragma unroll
    for (int r = 0; r < NPROJ; r++) {
        pj0[r] = proj[(2 * lane)     * NPROJ + r];
        pj1[r] = proj[(2 * lane + 1) * NPROJ + r];
    }

    const int total = BH * NSEQ;
    for (int row = gw; row < total; row += nw) {
        float2 x2 = *(const float2*)(x + (size_t)row * DIM + 2 * lane);
        float p[NPROJ];
#pragma unroll
        for (int r = 0; r < NPROJ; r++)
            p[r] = x2.x * pj0[r] + x2.y * pj1[r];
#pragma unroll
        for (int off = 16; off > 0; off >>= 1) {
#pragma unroll
            for (int r = 0; r < NPROJ; r++)
                p[r] += __shfl_xor_sync(0xffffffffu, p[r], off);
        }
        if (lane == 0) {
            int c = 0;
#pragma unroll
            for (int r = 0; r < NPROJ; r++)
                c |= (p[r] > 0.0f ? 1 : 0) << r;
            out[row] = (unsigned char)(c ^ (c >> 1));
        }
    }
}

// ---------------------------------------------------------------------------
// Kernel 2: per-(b,h) stable counting sort (exactly matches stable argsort).
// 128 threads, 128 segments of 64 elements, 128 buckets.
// ---------------------------------------------------------------------------
__global__ void sort_kernel(int which) {
    __shared__ unsigned char  h[NSEQ];
    __shared__ unsigned short seg[NSEG * ST];
    __shared__ int base[NBUCK];
    __shared__ int total[NBUCK];

    const int bh = blockIdx.x;
    const int t  = threadIdx.x;           // 0..127
    const unsigned char* hp = g_hash[which] + bh * NSEQ;
    int* op = g_idx[which] + bh * NSEQ;

    for (int i = t; i < NSEQ; i += NSEG) h[i] = hp[i];
    for (int i = t; i < NSEG * ST; i += NSEG) seg[i] = 0;
    __syncthreads();

    {   // per-segment histogram (sequential within segment => stable)
        unsigned short* row = seg + t * ST;
        const int b0 = t * SEGLEN;
        for (int k2 = 0; k2 < SEGLEN; k2++) row[h[b0 + k2]]++;
    }
    __syncthreads();

    {   // exclusive prefix over segments, per bucket (thread t = bucket t)
        int run = 0;
        for (int s = 0; s < NSEG; s++) {
            int c = seg[s * ST + t];
            seg[s * ST + t] = (unsigned short)run;
            run += c;
        }
        total[t] = run;
    }
    __syncthreads();

    if (t == 0) {   // exclusive scan of bucket totals
        int run = 0;
        for (int vv = 0; vv < NBUCK; vv++) { base[vv] = run; run += total[vv]; }
    }
    __syncthreads();

    {   // stable placement
        unsigned short* row = seg + t * ST;
        const int b0 = t * SEGLEN;
        for (int k2 = 0; k2 < SEGLEN; k2++) {
            int i = b0 + k2;
            int vv = h[i];
            int pos = base[vv] + row[vv];
            row[vv]++;
            op[pos] = i;
        }
    }
}

// ---------------------------------------------------------------------------
// Kernel 3: fused attention.
// Grid (32 qblocks, 32 bh), 256 threads = one sorted query per thread.
// Keys: chunk 0..3 = this block's 256 sorted keys (bias 0);
//       chunk 4..7 = 256 sampled keys (bias = +log 32, or -1e30 if the
//       sampled key's block == this query block).
// Online softmax over all 512 keys == reference's two-part LSE combine.
// ---------------------------------------------------------------------------
#define CHUNK 64
#define GROUP 8

__global__ __launch_bounds__(256, 1)
void attn_kernel(const float* __restrict__ q, const float* __restrict__ k,
                 const float* __restrict__ v, const int* __restrict__ sampled,
                 float* __restrict__ out) {
    __shared__ __align__(16) float Ksm[CHUNK][DIM];
    __shared__ __align__(16) float Vsm[CHUNK][DIM];
    __shared__ float addv[CHUNK];

    const int qb = blockIdx.x;
    const int bh = blockIdx.y;
    const int t  = threadIdx.x;

    const size_t bhBase = (size_t)bh * NSEQ;
    const int* qidx = g_idx[0] + bhBase;
    const int* kidx = g_idx[1] + bhBase;
    const int* smp  = sampled + bh * 256;

    const int qrow = qidx[qb * 256 + t];
    const float* qp = q + (bhBase + qrow) * DIM;

    // load query, pre-scaled by D^-0.5 = 0.125 (exact power of two)
    ull q2[32];
#pragma unroll
    for (int u = 0; u < 16; u++) {
        float4 f = ((const float4*)qp)[u];
        q2[2 * u]     = pk2(f.x * 0.125f, f.y * 0.125f);
        q2[2 * u + 1] = pk2(f.z * 0.125f, f.w * 0.125f);
    }

    float m = -__int_as_float(0x7f800000);  // -inf
    float l = 0.0f;
    ull acc[32];
#pragma unroll
    for (int i = 0; i < 32; i++) acc[i] = 0ull;

#pragma unroll 1
    for (int c = 0; c < 8; c++) {
        __syncthreads();
        {   // cooperative load of 64 (key,value) rows; 4 threads per row
            const int j   = t >> 2;
            const int sub = t & 3;
            const int kk  = c * CHUNK + j;
            int srow; float ad;
            if (kk < 256) { srow = qb * 256 + kk; ad = 0.0f; }
            else {
                int sj = smp[kk - 256];
                srow = sj;
                ad = ((sj >> 8) == qb) ? BIGNEG : LOG32;
            }
            const int krow = kidx[srow];
            const float4* kr = (const float4*)(k + (bhBase + krow) * DIM) + sub * 4;
            const float4* vr = (const float4*)(v + (bhBase + krow) * DIM) + sub * 4;
            float4* kd = (float4*)&Ksm[j][sub * 16];
            float4* vd = (float4*)&Vsm[j][sub * 16];
#pragma unroll
            for (int u = 0; u < 4; u++) { kd[u] = kr[u]; vd[u] = vr[u]; }
            if (sub == 0) addv[j] = ad;
        }
        __syncthreads();

#pragma unroll 1
        for (int g = 0; g < CHUNK / GROUP; g++) {
            float s[GROUP];
#pragma unroll
            for (int jj = 0; jj < GROUP; jj++) {
                const int jr = g * GROUP + jj;
                const ulonglong2* kp = (const ulonglong2*)&Ksm[jr][0];
                ull t0 = 0ull, t1 = 0ull;
#pragma unroll
                for (int dd = 0; dd < 16; dd++) {
                    ulonglong2 kv = kp[dd];
                    t0 = f2fma(q2[2 * dd],     kv.x, t0);
                    t1 = f2fma(q2[2 * dd + 1], kv.y, t1);
                }
                float a, b, cc, dd2;
                upk2(t0, a, b); upk2(t1, cc, dd2);
                s[jj] = (a + cc) + (b + dd2) + addv[jr];
            }
            float gm = s[0];
#pragma unroll
            for (int jj = 1; jj < GROUP; jj++) gm = fmaxf(gm, s[jj]);
            const float mn = fmaxf(m, gm);
            const float sc = __expf(m - mn);
            l *= sc;
            const ull sc2 = pk2(sc, sc);
#pragma unroll
            for (int d = 0; d < 32; d++) acc[d] = f2mul(acc[d], sc2);
#pragma unroll
            for (int jj = 0; jj < GROUP; jj++) {
                const int jr = g * GROUP + jj;
                const float p = __expf(s[jj] - mn);
                l += p;
                const ull p2 = pk2(p, p);
                const ulonglong2* vp = (const ulonglong2*)&Vsm[jr][0];
#pragma unroll
                for (int dd = 0; dd < 16; dd++) {
                    ulonglong2 vv = vp[dd];
                    acc[2 * dd]     = f2fma(p2, vv.x, acc[2 * dd]);
                    acc[2 * dd + 1] = f2fma(p2, vv.y, acc[2 * dd + 1]);
                }
            }
            m = mn;
        }
    }

    // normalize + scatter back to original query order (gather by q_idx_inv
    // == scatter by q_idx)
    const float inv = 1.0f / l;
    float* op = out + (bhBase + qrow) * DIM;
#pragma unroll
    for (int d = 0; d < 32; d++) {
        float a, b; upk2(acc[d], a, b);
        op[2 * d]     = a * inv;
        op[2 * d + 1] = b * inv;
    }
}

// ---------------------------------------------------------------------------
extern "C" void kernel_launch(void* const* d_in, const int* in_sizes, int n_in,
                              void* d_out, int out_size) {
    (void)in_sizes; (void)n_in; (void)out_size;
    const float* q    = (const float*)d_in[0];
    const float* k    = (const float*)d_in[1];
    const float* v    = (const float*)d_in[2];
    const float* proj = (const float*)d_in[3];
    const int*   smp  = (const int*)d_in[4];
    float* out = (float*)d_out;

    hash_kernel<<<512, 256>>>(q, proj, 0);
    hash_kernel<<<512, 256>>>(k, proj, 1);
    sort_kernel<<<32, 128>>>(0);
    sort_kernel<<<32, 128>>>(1);
    attn_kernel<<<dim3(32, 32), 256>>>(q, k, v, smp, out);
}

// round 6
// speedup vs baseline: 3.3444x; 3.3444x over previous
#include <cuda_runtime.h>
#include <cuda_fp16.h>
#include <cstdint>

// ---------------------------------------------------------------------------
// HyperAttention on GB300 (sm_103 baseline PTX): mma.sync m16n8k16 flash
// attention with fixed-shift softmax.  B=2,H=16,N=8192,D=64.
// CTA = 128 sorted queries x 512 keys (8 chunks of 64).
// ---------------------------------------------------------------------------

#define BH      32
#define NSEQ    8192
#define DIM     64
#define NPROJ   7
#define NBUCK   128
#define NSEG    128
#define SEGLEN  64
#define ST      130
#define LOG32   3.4657359027997265f
#define BIGNEG  (-1e30f)
#define M_FIX   6.0f

__device__ unsigned char g_hash[2][BH * NSEQ];
__device__ int           g_idx[2][BH * NSEQ];   // [0]=q_idx, [1]=k_idx

// ===================== helpers =============================================
__device__ __forceinline__ uint32_t smem_u32(const void* p) {
    uint32_t a;
    asm("{ .reg .u64 t; cvta.to.shared.u64 t, %1; cvt.u32.u64 %0, t; }"
        : "=r"(a) : "l"(p));
    return a;
}
__device__ __forceinline__ uint32_t swz(uint32_t o) { return o ^ ((o >> 3) & 0x70); }

__device__ __forceinline__ void mma16816(float* c, const uint32_t* a,
                                         uint32_t b0, uint32_t b1) {
    asm volatile(
        "mma.sync.aligned.m16n8k16.row.col.f32.f16.f16.f32 "
        "{%0,%1,%2,%3}, {%4,%5,%6,%7}, {%8,%9}, {%0,%1,%2,%3};"
        : "+f"(c[0]), "+f"(c[1]), "+f"(c[2]), "+f"(c[3])
        : "r"(a[0]), "r"(a[1]), "r"(a[2]), "r"(a[3]), "r"(b0), "r"(b1));
}
__device__ __forceinline__ void ldsm4(uint32_t* r, uint32_t addr) {
    asm volatile("ldmatrix.sync.aligned.m8n8.x4.shared.b16 {%0,%1,%2,%3}, [%4];"
        : "=r"(r[0]), "=r"(r[1]), "=r"(r[2]), "=r"(r[3]) : "r"(addr));
}
__device__ __forceinline__ void ldsm4t(uint32_t* r, uint32_t addr) {
    asm volatile("ldmatrix.sync.aligned.m8n8.x4.trans.shared.b16 {%0,%1,%2,%3}, [%4];"
        : "=r"(r[0]), "=r"(r[1]), "=r"(r[2]), "=r"(r[3]) : "r"(addr));
}
// split float2 into hi/lo fp16 pairs (packed b32)
__device__ __forceinline__ void split2(float x, float y, uint32_t& hi, uint32_t& lo) {
    __half hx = __float2half_rn(x), hy = __float2half_rn(y);
    __half lx = __float2half_rn(x - __half2float(hx));
    __half ly = __float2half_rn(y - __half2float(hy));
    half2 H = __halves2half2(hx, hy), L = __halves2half2(lx, ly);
    hi = *(uint32_t*)&H; lo = *(uint32_t*)&L;
}

// ---------------------------------------------------------------------------
// LSH hash (q and k fused via blockIdx.y)
// ---------------------------------------------------------------------------
__global__ void hash_kernel(const float* __restrict__ q,
                            const float* __restrict__ k,
                            const float* __restrict__ proj) {
    const int which = blockIdx.y;
    const float* x = which ? k : q;
    unsigned char* out = g_hash[which];
    const int lane = threadIdx.x & 31;
    const int gw = (blockIdx.x * blockDim.x + threadIdx.x) >> 5;
    const int nw = (gridDim.x * blockDim.x) >> 5;
    float pj0[NPROJ], pj1[NPROJ];
#pragma unroll
    for (int r = 0; r < NPROJ; r++) {
        pj0[r] = proj[(2 * lane) * NPROJ + r];
        pj1[r] = proj[(2 * lane + 1) * NPROJ + r];
    }
    const int total = BH * NSEQ;
    for (int row = gw; row < total; row += nw) {
        float2 x2 = *(const float2*)(x + (size_t)row * DIM + 2 * lane);
        float p[NPROJ];
#pragma unroll
        for (int r = 0; r < NPROJ; r++) p[r] = x2.x * pj0[r] + x2.y * pj1[r];
#pragma unroll
        for (int off = 16; off > 0; off >>= 1)
#pragma unroll
            for (int r = 0; r < NPROJ; r++)
                p[r] += __shfl_xor_sync(0xffffffffu, p[r], off);
        if (lane == 0) {
            int c = 0;
#pragma unroll
            for (int r = 0; r < NPROJ; r++) c |= (p[r] > 0.0f ? 1 : 0) << r;
            out[row] = (unsigned char)(c ^ (c >> 1));
        }
    }
}

// ---------------------------------------------------------------------------
// stable counting sort (q and k fused: grid 64)
// ---------------------------------------------------------------------------
__global__ void sort_kernel() {
    __shared__ unsigned char  h[NSEQ];
    __shared__ unsigned short seg[NSEG * ST];
    __shared__ int base[NBUCK];
    __shared__ int tot[NBUCK];
    const int which = blockIdx.x >> 5;
    const int bh = blockIdx.x & 31;
    const int t = threadIdx.x;
    const unsigned char* hp = g_hash[which] + bh * NSEQ;
    int* op = g_idx[which] + bh * NSEQ;
    for (int i = t; i < NSEQ; i += NSEG) h[i] = hp[i];
    for (int i = t; i < NSEG * ST; i += NSEG) seg[i] = 0;
    __syncthreads();
    {
        unsigned short* row = seg + t * ST;
        const int b0 = t * SEGLEN;
        for (int k2 = 0; k2 < SEGLEN; k2++) row[h[b0 + k2]]++;
    }
    __syncthreads();
    {
        int run = 0;
        for (int s = 0; s < NSEG; s++) {
            int c = seg[s * ST + t];
            seg[s * ST + t] = (unsigned short)run;
            run += c;
        }
        tot[t] = run;
    }
    __syncthreads();
    if (t == 0) {
        int run = 0;
        for (int vv = 0; vv < NBUCK; vv++) { base[vv] = run; run += tot[vv]; }
    }
    __syncthreads();
    {
        unsigned short* row = seg + t * ST;
        const int b0 = t * SEGLEN;
        for (int k2 = 0; k2 < SEGLEN; k2++) {
            int i = b0 + k2;
            int vv = h[i];
            op[base[vv] + row[vv]] = i;
            row[vv]++;
        }
    }
}

// ---------------------------------------------------------------------------
// fused attention: grid (64 q-halves, 32 bh), 256 threads (8 warps x 16 rows)
// ---------------------------------------------------------------------------
__global__ __launch_bounds__(256, 2)
void attn_kernel(const float* __restrict__ q, const float* __restrict__ k,
                 const float* __restrict__ v, const int* __restrict__ sampled,
                 float* __restrict__ out) {
    __shared__ __align__(128) char KsmB[64 * 128];
    __shared__ __align__(128) char VhiB[64 * 128];
    __shared__ __align__(128) char VloB[64 * 128];
    __shared__ float addv[64];

    const int tid  = threadIdx.x;
    const int w    = tid >> 5;
    const int lane = tid & 31;
    const int qhalf = blockIdx.x;
    const int qb    = qhalf >> 1;
    const int bh    = blockIdx.y;
    const size_t bhBase = (size_t)bh * NSEQ;
    const int* qidx = g_idx[0] + bhBase;
    const int* kidx = g_idx[1] + bhBase;
    const int* smp  = sampled + bh * 256;

    const uint32_t Ksm = smem_u32(KsmB);
    const uint32_t Vhs = smem_u32(VhiB);
    const uint32_t Vls = smem_u32(VloB);

    // ---- Q fragments, loaded directly from gmem (hi/lo split, scaled) ----
    const int r0 = 16 * w + (lane >> 2);
    const int qrow0 = qidx[qhalf * 128 + r0];
    const int qrow1 = qidx[qhalf * 128 + r0 + 8];
    const float* q0p = q + (bhBase + qrow0) * DIM;
    const float* q1p = q + (bhBase + qrow1) * DIM;

    uint32_t qh[4][4], ql[4][4];
#pragma unroll
    for (int s = 0; s < 4; s++) {
        const int d = 16 * s + (lane & 3) * 2;
        float2 f00 = *(const float2*)(q0p + d);
        float2 f10 = *(const float2*)(q1p + d);
        float2 f01 = *(const float2*)(q0p + d + 8);
        float2 f11 = *(const float2*)(q1p + d + 8);
        split2(f00.x * 0.125f, f00.y * 0.125f, qh[s][0], ql[s][0]);
        split2(f10.x * 0.125f, f10.y * 0.125f, qh[s][1], ql[s][1]);
        split2(f01.x * 0.125f, f01.y * 0.125f, qh[s][2], ql[s][2]);
        split2(f11.x * 0.125f, f11.y * 0.125f, qh[s][3], ql[s][3]);
    }

    float O[8][4];
#pragma unroll
    for (int g = 0; g < 8; g++)
#pragma unroll
        for (int e = 0; e < 4; e++) O[g][e] = 0.0f;
    float lsum0 = 0.0f, lsum1 = 0.0f;

#pragma unroll 1
    for (int c = 0; c < 8; c++) {
        if (c) __syncthreads();
        // ---- gather + convert 64 (key,value) rows ----
        {
            const int j   = tid >> 2;       // key row 0..63
            const int sub = tid & 3;        // dim quarter
            const int kk  = c * 64 + j;
            int srow; float ad;
            if (kk < 256) { srow = qb * 256 + kk; ad = -M_FIX; }
            else {
                int sj = smp[kk - 256];
                srow = sj;
                ad = ((sj >> 8) == qb) ? BIGNEG : (LOG32 - M_FIX);
            }
            if (sub == 0) addv[j] = ad;
            const int krow = kidx[srow];
            const float4* ks = (const float4*)(k + (bhBase + krow) * DIM) + sub * 4;
            const float4* vs = (const float4*)(v + (bhBase + krow) * DIM) + sub * 4;
            __half kh16[16], vh16[16], vl16[16];
#pragma unroll
            for (int u = 0; u < 4; u++) {
                float4 f = ks[u];
                kh16[4 * u + 0] = __float2half_rn(f.x);
                kh16[4 * u + 1] = __float2half_rn(f.y);
                kh16[4 * u + 2] = __float2half_rn(f.z);
                kh16[4 * u + 3] = __float2half_rn(f.w);
                float4 g4 = vs[u];
                float a[4] = {g4.x, g4.y, g4.z, g4.w};
#pragma unroll
                for (int e = 0; e < 4; e++) {
                    __half hh = __float2half_rn(a[e]);
                    vh16[4 * u + e] = hh;
                    vl16[4 * u + e] = __float2half_rn(a[e] - __half2float(hh));
                }
            }
            const uint32_t o0 = swz((uint32_t)(j * 128 + sub * 32));
            const uint32_t o1 = swz((uint32_t)(j * 128 + sub * 32 + 16));
            *(uint4*)(KsmB + o0) = ((uint4*)kh16)[0];
            *(uint4*)(KsmB + o1) = ((uint4*)kh16)[1];
            *(uint4*)(VhiB + o0) = ((uint4*)vh16)[0];
            *(uint4*)(VhiB + o1) = ((uint4*)vh16)[1];
            *(uint4*)(VloB + o0) = ((uint4*)vl16)[0];
            *(uint4*)(VloB + o1) = ((uint4*)vl16)[1];
        }
        __syncthreads();

        // ---- S = Q . K^T  (per-warp 16x64, fp32 frags) ----
        float S[8][4];
#pragma unroll
        for (int g = 0; g < 8; g++)
#pragma unroll
            for (int e = 0; e < 4; e++) S[g][e] = 0.0f;

#pragma unroll
        for (int g = 0; g < 8; g++) {
            uint32_t kb[8];
            const uint32_t key = 8u * g + (lane & 7);
            const uint32_t dv  = ((uint32_t)(lane >> 3) & 3u) * 8u;
            ldsm4(kb,     Ksm + swz(key * 128 + dv * 2));
            ldsm4(kb + 4, Ksm + swz(key * 128 + (32 + dv) * 2));
#pragma unroll
            for (int s = 0; s < 4; s++) mma16816(S[g], qh[s], kb[2 * s], kb[2 * s + 1]);
#pragma unroll
            for (int s = 0; s < 4; s++) mma16816(S[g], ql[s], kb[2 * s], kb[2 * s + 1]);
        }

        // ---- softmax (fixed shift) -> P fp16 fragments ----
        uint32_t P01[8], P23[8];
#pragma unroll
        for (int g = 0; g < 8; g++) {
            const int n0 = 8 * g + (lane & 3) * 2;
            const float av0 = addv[n0], av1 = addv[n0 + 1];
            float e0 = __expf(S[g][0] + av0);
            float e1 = __expf(S[g][1] + av1);
            float e2 = __expf(S[g][2] + av0);
            float e3 = __expf(S[g][3] + av1);
            lsum0 += e0 + e1;
            lsum1 += e2 + e3;
            half2 h01 = __floats2half2_rn(e0, e1);
            half2 h23 = __floats2half2_rn(e2, e3);
            P01[g] = *(uint32_t*)&h01;
            P23[g] = *(uint32_t*)&h23;
        }

        // ---- O += P . (Vhi + Vlo) ----
#pragma unroll
        for (int j = 0; j < 4; j++) {             // key steps of 16
            uint32_t A[4] = {P01[2 * j], P23[2 * j], P01[2 * j + 1], P23[2 * j + 1]};
            const uint32_t key = 16u * j + ((uint32_t)lane & 15u);
            const uint32_t dof = ((uint32_t)(lane >> 4) & 1u) * 8u;
#pragma unroll
            for (int dg = 0; dg < 4; dg++) {      // dim groups of 16
                uint32_t vb[4];
                ldsm4t(vb, Vhs + swz(key * 128 + (16u * dg + dof) * 2));
                mma16816(O[2 * dg],     A, vb[0], vb[1]);
                mma16816(O[2 * dg + 1], A, vb[2], vb[3]);
                ldsm4t(vb, Vls + swz(key * 128 + (16u * dg + dof) * 2));
                mma16816(O[2 * dg],     A, vb[0], vb[1]);
                mma16816(O[2 * dg + 1], A, vb[2], vb[3]);
            }
        }
    }

    // ---- epilogue: row sums across the quad, normalize, store ----
    lsum0 += __shfl_xor_sync(0xffffffffu, lsum0, 1);
    lsum0 += __shfl_xor_sync(0xffffffffu, lsum0, 2);
    lsum1 += __shfl_xor_sync(0xffffffffu, lsum1, 1);
    lsum1 += __shfl_xor_sync(0xffffffffu, lsum1, 2);
    const float inv0 = 1.0f / lsum0;
    const float inv1 = 1.0f / lsum1;

    float* o0p = out + (bhBase + qrow0) * DIM;
    float* o1p = out + (bhBase + qrow1) * DIM;
#pragma unroll
    for (int g = 0; g < 8; g++) {
        const int n0 = 8 * g + (lane & 3) * 2;
        float2 a = {O[g][0] * inv0, O[g][1] * inv0};
        float2 b = {O[g][2] * inv1, O[g][3] * inv1};
        *(float2*)(o0p + n0) = a;
        *(float2*)(o1p + n0) = b;
    }
}

// ---------------------------------------------------------------------------
extern "C" void kernel_launch(void* const* d_in, const int* in_sizes, int n_in,
                              void* d_out, int out_size) {
    (void)in_sizes; (void)n_in; (void)out_size;
    const float* q    = (const float*)d_in[0];
    const float* k    = (const float*)d_in[1];
    const float* v    = (const float*)d_in[2];
    const float* proj = (const float*)d_in[3];
    const int*   smp  = (const int*)d_in[4];
    float* out = (float*)d_out;

    hash_kernel<<<dim3(256, 2), 256>>>(q, k, proj);
    sort_kernel<<<64, 128>>>();
    attn_kernel<<<dim3(64, 32), 256>>>(q, k, v, smp, out);
}

// round 7
// speedup vs baseline: 4.3101x; 1.2888x over previous
#include <cuda_runtime.h>
#include <cuda_fp16.h>
#include <cstdint>

// ---------------------------------------------------------------------------
// HyperAttention on GB300 (sm_103 baseline PTX): mma.sync m16n8k16 flash
// attention with fixed-shift softmax (log2 domain).  B=2,H=16,N=8192,D=64.
// CTA = 128 sorted queries x 512 keys (8 chunks of 64).
// ---------------------------------------------------------------------------

#define BH      32
#define NSEQ    8192
#define DIM     64
#define NPROJ   7
#define NBUCK   128
#define NSEG    128
#define SEGLEN  64
#define ST      130
#define LOG32   3.4657359027997265f
#define BIGNEG  (-1e30f)
#define M_FIX   6.0f
#define LOG2E   1.4426950408889634f

__device__ unsigned char g_hash[2][BH * NSEQ];
__device__ int           g_idx[2][BH * NSEQ];   // [0]=q_idx, [1]=k_idx

// ===================== helpers =============================================
__device__ __forceinline__ uint32_t smem_u32(const void* p) {
    uint32_t a;
    asm("{ .reg .u64 t; cvta.to.shared.u64 t, %1; cvt.u32.u64 %0, t; }"
        : "=r"(a) : "l"(p));
    return a;
}
__device__ __forceinline__ uint32_t swz(uint32_t o) { return o ^ ((o >> 3) & 0x70); }

__device__ __forceinline__ float ex2f(float x) {
    float y; asm("ex2.approx.ftz.f32 %0, %1;" : "=f"(y) : "f"(x)); return y;
}
__device__ __forceinline__ void mma16816(float* c, const uint32_t* a,
                                         uint32_t b0, uint32_t b1) {
    asm volatile(
        "mma.sync.aligned.m16n8k16.row.col.f32.f16.f16.f32 "
        "{%0,%1,%2,%3}, {%4,%5,%6,%7}, {%8,%9}, {%0,%1,%2,%3};"
        : "+f"(c[0]), "+f"(c[1]), "+f"(c[2]), "+f"(c[3])
        : "r"(a[0]), "r"(a[1]), "r"(a[2]), "r"(a[3]), "r"(b0), "r"(b1));
}
__device__ __forceinline__ void ldsm4(uint32_t* r, uint32_t addr) {
    asm volatile("ldmatrix.sync.aligned.m8n8.x4.shared.b16 {%0,%1,%2,%3}, [%4];"
        : "=r"(r[0]), "=r"(r[1]), "=r"(r[2]), "=r"(r[3]) : "r"(addr));
}
__device__ __forceinline__ void ldsm4t(uint32_t* r, uint32_t addr) {
    asm volatile("ldmatrix.sync.aligned.m8n8.x4.trans.shared.b16 {%0,%1,%2,%3}, [%4];"
        : "=r"(r[0]), "=r"(r[1]), "=r"(r[2]), "=r"(r[3]) : "r"(addr));
}

// ---------------------------------------------------------------------------
// LSH hash: thread-per-row (q row AND k row of the same index).
// Bit-exact emulation of the validated warp-butterfly reduction:
//   per-"lane" partial  a[l] = x[2l]*p[2l] + x[2l+1]*p[2l+1]
//   then XOR-butterfly tree (off = 16,8,4,2,1) serialized in registers.
// ---------------------------------------------------------------------------
__global__ __launch_bounds__(256, 2)
void hash_kernel(const float* __restrict__ q,
                 const float* __restrict__ k,
                 const float* __restrict__ proj) {
    __shared__ float pjs[NPROJ][DIM];   // pjs[r][d] = proj[d*NPROJ + r]
    const int t = threadIdx.x;
    for (int i = t; i < DIM * NPROJ; i += 256)
        pjs[i % NPROJ][i / NPROJ] = proj[i];
    __syncthreads();

    const int row = blockIdx.x * 256 + t;     // 0 .. BH*NSEQ-1
    if (row >= BH * NSEQ) return;

#pragma unroll 1
    for (int which = 0; which < 2; which++) {
        const float* xp = (which ? k : q) + (size_t)row * DIM;
        float xr[DIM];
#pragma unroll
        for (int u = 0; u < 16; u++) {
            float4 f = ((const float4*)xp)[u];
            xr[4 * u] = f.x; xr[4 * u + 1] = f.y;
            xr[4 * u + 2] = f.z; xr[4 * u + 3] = f.w;
        }
        int code = 0;
#pragma unroll 1
        for (int r = 0; r < NPROJ; r++) {
            float a[32];
#pragma unroll
            for (int l = 0; l < 16; l++) {
                float4 p4 = *(const float4*)&pjs[r][4 * l];
                a[2 * l]     = xr[4 * l]     * p4.x + xr[4 * l + 1] * p4.y;
                a[2 * l + 1] = xr[4 * l + 2] * p4.z + xr[4 * l + 3] * p4.w;
            }
#pragma unroll
            for (int off = 16; off > 0; off >>= 1)
#pragma unroll
                for (int i = 0; i < 32; i++)
                    if (i < off) a[i] += a[i + off];
            code |= (a[0] > 0.0f ? 1 : 0) << r;
        }
        g_hash[which][row] = (unsigned char)(code ^ (code >> 1));
    }
}

// ---------------------------------------------------------------------------
// stable counting sort (q and k fused: grid 64)
// ---------------------------------------------------------------------------
__global__ void sort_kernel() {
    __shared__ unsigned char  h[NSEQ];
    __shared__ unsigned short seg[NSEG * ST];
    __shared__ int base[NBUCK];
    __shared__ int tot[NBUCK];
    const int which = blockIdx.x >> 5;
    const int bh = blockIdx.x & 31;
    const int t = threadIdx.x;
    const unsigned char* hp = g_hash[which] + bh * NSEQ;
    int* op = g_idx[which] + bh * NSEQ;
    for (int i = t; i < NSEQ; i += NSEG) h[i] = hp[i];
    for (int i = t; i < NSEG * ST; i += NSEG) seg[i] = 0;
    __syncthreads();
    {
        unsigned short* row = seg + t * ST;
        const int b0 = t * SEGLEN;
        for (int k2 = 0; k2 < SEGLEN; k2++) row[h[b0 + k2]]++;
    }
    __syncthreads();
    {
        int run = 0;
        for (int s = 0; s < NSEG; s++) {
            int c = seg[s * ST + t];
            seg[s * ST + t] = (unsigned short)run;
            run += c;
        }
        tot[t] = run;
    }
    __syncthreads();
    if (t == 0) {
        int run = 0;
        for (int vv = 0; vv < NBUCK; vv++) { base[vv] = run; run += tot[vv]; }
    }
    __syncthreads();
    {
        unsigned short* row = seg + t * ST;
        const int b0 = t * SEGLEN;
        for (int k2 = 0; k2 < SEGLEN; k2++) {
            int i = b0 + k2;
            int vv = h[i];
            op[base[vv] + row[vv]] = i;
            row[vv]++;
        }
    }
}

// ---------------------------------------------------------------------------
// fused attention: grid (64 q-halves, 32 bh), 256 threads (8 warps x 16 rows)
// Q single fp16 (scaled by 0.125*log2e); K fp16; V hi/lo split.
// softmax in log2 domain: p = ex2(S + bias')  with bias' pre-scaled by log2e.
// ---------------------------------------------------------------------------
__global__ __launch_bounds__(256, 2)
void attn_kernel(const float* __restrict__ q, const float* __restrict__ k,
                 const float* __restrict__ v, const int* __restrict__ sampled,
                 float* __restrict__ out) {
    __shared__ __align__(128) char KsmB[64 * 128];
    __shared__ __align__(128) char VhiB[64 * 128];
    __shared__ __align__(128) char VloB[64 * 128];
    __shared__ float addv[64];

    const int tid  = threadIdx.x;
    const int w    = tid >> 5;
    const int lane = tid & 31;
    const int qhalf = blockIdx.x;
    const int qb    = qhalf >> 1;
    const int bh    = blockIdx.y;
    const size_t bhBase = (size_t)bh * NSEQ;
    const int* qidx = g_idx[0] + bhBase;
    const int* kidx = g_idx[1] + bhBase;
    const int* smp  = sampled + bh * 256;

    const uint32_t Ksm = smem_u32(KsmB);
    const uint32_t Vhs = smem_u32(VhiB);
    const uint32_t Vls = smem_u32(VloB);

    // ---- Q fragments straight from gmem (single fp16, scaled) ----
    const int r0 = 16 * w + (lane >> 2);
    const int qrow0 = qidx[qhalf * 128 + r0];
    const int qrow1 = qidx[qhalf * 128 + r0 + 8];
    const float* q0p = q + (bhBase + qrow0) * DIM;
    const float* q1p = q + (bhBase + qrow1) * DIM;
    const float qsc = 0.125f * LOG2E;

    uint32_t qh[4][4];
#pragma unroll
    for (int s = 0; s < 4; s++) {
        const int d = 16 * s + (lane & 3) * 2;
        float2 f00 = *(const float2*)(q0p + d);
        float2 f10 = *(const float2*)(q1p + d);
        float2 f01 = *(const float2*)(q0p + d + 8);
        float2 f11 = *(const float2*)(q1p + d + 8);
        half2 h;
        h = __floats2half2_rn(f00.x * qsc, f00.y * qsc); qh[s][0] = *(uint32_t*)&h;
        h = __floats2half2_rn(f10.x * qsc, f10.y * qsc); qh[s][1] = *(uint32_t*)&h;
        h = __floats2half2_rn(f01.x * qsc, f01.y * qsc); qh[s][2] = *(uint32_t*)&h;
        h = __floats2half2_rn(f11.x * qsc, f11.y * qsc); qh[s][3] = *(uint32_t*)&h;
    }

    float O[8][4];
#pragma unroll
    for (int g = 0; g < 8; g++)
#pragma unroll
        for (int e = 0; e < 4; e++) O[g][e] = 0.0f;
    float lsum0 = 0.0f, lsum1 = 0.0f;

#pragma unroll 1
    for (int c = 0; c < 8; c++) {
        if (c) __syncthreads();
        // ---- gather + convert 64 (key,value) rows ----
        {
            const int j   = tid >> 2;       // key row 0..63
            const int sub = tid & 3;        // dim quarter
            const int kk  = c * 64 + j;
            int srow; float ad;
            if (kk < 256) { srow = qb * 256 + kk; ad = -M_FIX * LOG2E; }
            else {
                int sj = smp[kk - 256];
                srow = sj;
                ad = ((sj >> 8) == qb) ? BIGNEG : ((LOG32 - M_FIX) * LOG2E);
            }
            if (sub == 0) addv[j] = ad;
            const int krow = kidx[srow];
            const float4* ks = (const float4*)(k + (bhBase + krow) * DIM) + sub * 4;
            const float4* vs = (const float4*)(v + (bhBase + krow) * DIM) + sub * 4;
            __half kh16[16], vh16[16], vl16[16];
#pragma unroll
            for (int u = 0; u < 4; u++) {
                float4 f = ks[u];
                kh16[4 * u + 0] = __float2half_rn(f.x);
                kh16[4 * u + 1] = __float2half_rn(f.y);
                kh16[4 * u + 2] = __float2half_rn(f.z);
                kh16[4 * u + 3] = __float2half_rn(f.w);
                float4 g4 = vs[u];
                float a[4] = {g4.x, g4.y, g4.z, g4.w};
#pragma unroll
                for (int e = 0; e < 4; e++) {
                    __half hh = __float2half_rn(a[e]);
                    vh16[4 * u + e] = hh;
                    vl16[4 * u + e] = __float2half_rn(a[e] - __half2float(hh));
                }
            }
            const uint32_t o0 = swz((uint32_t)(j * 128 + sub * 32));
            const uint32_t o1 = swz((uint32_t)(j * 128 + sub * 32 + 16));
            *(uint4*)(KsmB + o0) = ((uint4*)kh16)[0];
            *(uint4*)(KsmB + o1) = ((uint4*)kh16)[1];
            *(uint4*)(VhiB + o0) = ((uint4*)vh16)[0];
            *(uint4*)(VhiB + o1) = ((uint4*)vh16)[1];
            *(uint4*)(VloB + o0) = ((uint4*)vl16)[0];
            *(uint4*)(VloB + o1) = ((uint4*)vl16)[1];
        }
        __syncthreads();

        // ---- S = Q . K^T  (per-warp 16x64, fp32 frags, log2 domain) ----
        float S[8][4];
#pragma unroll
        for (int g = 0; g < 8; g++)
#pragma unroll
            for (int e = 0; e < 4; e++) S[g][e] = 0.0f;

#pragma unroll
        for (int g = 0; g < 8; g++) {
            uint32_t kb[8];
            const uint32_t key = 8u * g + (lane & 7);
            const uint32_t dv  = ((uint32_t)(lane >> 3) & 3u) * 8u;
            ldsm4(kb,     Ksm + swz(key * 128 + dv * 2));
            ldsm4(kb + 4, Ksm + swz(key * 128 + (32 + dv) * 2));
#pragma unroll
            for (int s = 0; s < 4; s++) mma16816(S[g], qh[s], kb[2 * s], kb[2 * s + 1]);
        }

        // ---- softmax (fixed shift, log2) -> P fp16 fragments ----
        uint32_t P01[8], P23[8];
#pragma unroll
        for (int g = 0; g < 8; g++) {
            const int n0 = 8 * g + (lane & 3) * 2;
            const float av0 = addv[n0], av1 = addv[n0 + 1];
            float e0 = ex2f(S[g][0] + av0);
            float e1 = ex2f(S[g][1] + av1);
            float e2 = ex2f(S[g][2] + av0);
            float e3 = ex2f(S[g][3] + av1);
            lsum0 += e0 + e1;
            lsum1 += e2 + e3;
            half2 h01 = __floats2half2_rn(e0, e1);
            half2 h23 = __floats2half2_rn(e2, e3);
            P01[g] = *(uint32_t*)&h01;
            P23[g] = *(uint32_t*)&h23;
        }

        // ---- O += P . (Vhi + Vlo) ----
#pragma unroll
        for (int j = 0; j < 4; j++) {             // key steps of 16
            uint32_t A[4] = {P01[2 * j], P23[2 * j], P01[2 * j + 1], P23[2 * j + 1]};
            const uint32_t key = 16u * j + ((uint32_t)lane & 15u);
            const uint32_t dof = ((uint32_t)(lane >> 4) & 1u) * 8u;
#pragma unroll
            for (int dg = 0; dg < 4; dg++) {      // dim groups of 16
                uint32_t vb[4];
                ldsm4t(vb, Vhs + swz(key * 128 + (16u * dg + dof) * 2));
                mma16816(O[2 * dg],     A, vb[0], vb[1]);
                mma16816(O[2 * dg + 1], A, vb[2], vb[3]);
                ldsm4t(vb, Vls + swz(key * 128 + (16u * dg + dof) * 2));
                mma16816(O[2 * dg],     A, vb[0], vb[1]);
                mma16816(O[2 * dg + 1], A, vb[2], vb[3]);
            }
        }
    }

    // ---- epilogue: row sums across the quad, normalize, store ----
    lsum0 += __shfl_xor_sync(0xffffffffu, lsum0, 1);
    lsum0 += __shfl_xor_sync(0xffffffffu, lsum0, 2);
    lsum1 += __shfl_xor_sync(0xffffffffu, lsum1, 1);
    lsum1 += __shfl_xor_sync(0xffffffffu, lsum1, 2);
    const float inv0 = 1.0f / lsum0;
    const float inv1 = 1.0f / lsum1;

    float* o0p = out + (bhBase + qrow0) * DIM;
    float* o1p = out + (bhBase + qrow1) * DIM;
#pragma unroll
    for (int g = 0; g < 8; g++) {
        const int n0 = 8 * g + (lane & 3) * 2;
        float2 a = {O[g][0] * inv0, O[g][1] * inv0};
        float2 b = {O[g][2] * inv1, O[g][3] * inv1};
        *(float2*)(o0p + n0) = a;
        *(float2*)(o1p + n0) = b;
    }
}

// ---------------------------------------------------------------------------
extern "C" void kernel_launch(void* const* d_in, const int* in_sizes, int n_in,
                              void* d_out, int out_size) {
    (void)in_sizes; (void)n_in; (void)out_size;
    const float* q    = (const float*)d_in[0];
    const float* k    = (const float*)d_in[1];
    const float* v    = (const float*)d_in[2];
    const float* proj = (const float*)d_in[3];
    const int*   smp  = (const int*)d_in[4];
    float* out = (float*)d_out;

    hash_kernel<<<(BH * NSEQ + 255) / 256, 256>>>(q, k, proj);
    sort_kernel<<<64, 128>>>();
    attn_kernel<<<dim3(64, 32), 256>>>(q, k, v, smp, out);
}

// round 8
// speedup vs baseline: 4.5350x; 1.0522x over previous
#include <cuda_runtime.h>
#include <cuda_fp16.h>
#include <cstdint>

// ---------------------------------------------------------------------------
// HyperAttention on GB300 (sm_103 baseline PTX): mma.sync m16n8k16 flash
// attention with fixed-shift softmax (log2 domain).  B=2,H=16,N=8192,D=64.
// CTA = 128 sorted queries x 512 keys (8 chunks of 64).
// ---------------------------------------------------------------------------

#define BH      32
#define NSEQ    8192
#define DIM     64
#define NPROJ   7
#define NBUCK   128
#define NSEG    128
#define SEGLEN  64
#define ST      130
#define LOG32   3.4657359027997265f
#define BIGNEG  (-1e30f)
#define M_FIX   6.0f
#define LOG2E   1.4426950408889634f

__device__ unsigned char g_hash[2][BH * NSEQ];
__device__ int           g_idx[2][BH * NSEQ];   // [0]=q_idx, [1]=k_idx

// ===================== helpers =============================================
__device__ __forceinline__ uint32_t smem_u32(const void* p) {
    uint32_t a;
    asm("{ .reg .u64 t; cvta.to.shared.u64 t, %1; cvt.u32.u64 %0, t; }"
        : "=r"(a) : "l"(p));
    return a;
}
__device__ __forceinline__ uint32_t swz(uint32_t o) { return o ^ ((o >> 3) & 0x70); }

__device__ __forceinline__ float ex2f(float x) {
    float y; asm("ex2.approx.ftz.f32 %0, %1;" : "=f"(y) : "f"(x)); return y;
}
__device__ __forceinline__ void mma16816(float* c, const uint32_t* a,
                                         uint32_t b0, uint32_t b1) {
    asm volatile(
        "mma.sync.aligned.m16n8k16.row.col.f32.f16.f16.f32 "
        "{%0,%1,%2,%3}, {%4,%5,%6,%7}, {%8,%9}, {%0,%1,%2,%3};"
        : "+f"(c[0]), "+f"(c[1]), "+f"(c[2]), "+f"(c[3])
        : "r"(a[0]), "r"(a[1]), "r"(a[2]), "r"(a[3]), "r"(b0), "r"(b1));
}
__device__ __forceinline__ void ldsm4(uint32_t* r, uint32_t addr) {
    asm volatile("ldmatrix.sync.aligned.m8n8.x4.shared.b16 {%0,%1,%2,%3}, [%4];"
        : "=r"(r[0]), "=r"(r[1]), "=r"(r[2]), "=r"(r[3]) : "r"(addr));
}
__device__ __forceinline__ void ldsm4t(uint32_t* r, uint32_t addr) {
    asm volatile("ldmatrix.sync.aligned.m8n8.x4.trans.shared.b16 {%0,%1,%2,%3}, [%4];"
        : "=r"(r[0]), "=r"(r[1]), "=r"(r[2]), "=r"(r[3]) : "r"(addr));
}

// ---------------------------------------------------------------------------
// LSH hash: 8 lanes per row (4 rows per warp), proj held in registers.
// Reduction is BIT-EXACT to the validated tree:
//   leaves a[i] = x[2i]*p[2i] + x[2i+1]*p[2i+1]   (i = 0..31)
//   stages off=16,8 are lane-local adds; off=4,2,1 via xor-butterfly
//   (lane j==0 result identical to sequential a[i]+=a[i+off]).
// ---------------------------------------------------------------------------
__global__ __launch_bounds__(256)
void hash_kernel(const float* __restrict__ q,
                 const float* __restrict__ k,
                 const float* __restrict__ proj) {
    __shared__ float pjs[NPROJ][DIM];   // pjs[r][d] = proj[d*NPROJ + r]
    const int t = threadIdx.x;
    for (int i = t; i < DIM * NPROJ; i += 256)
        pjs[i % NPROJ][i / NPROJ] = proj[i];
    __syncthreads();

    const int lane = t & 31;
    const int j = lane & 7;            // dim octet within row
    // per-lane proj registers: dims {2j,2j+1}, +16, +32, +48 for each r
    float2 pr[NPROJ][4];
#pragma unroll
    for (int r = 0; r < NPROJ; r++)
#pragma unroll
        for (int e = 0; e < 4; e++)
            pr[r][e] = *(const float2*)&pjs[r][2 * j + 16 * e];

    const int gw = (blockIdx.x * 256 + t) >> 5;   // global warp id
    const int nw = (gridDim.x * 256) >> 5;
    const int ngrp = (BH * NSEQ) / 4;

    for (int grp = gw; grp < ngrp; grp += nw) {
        const int row = grp * 4 + (lane >> 3);
#pragma unroll 1
        for (int which = 0; which < 2; which++) {
            const float* xp = (which ? k : q) + (size_t)row * DIM + 2 * j;
            const float2 x0 = *(const float2*)(xp);
            const float2 x1 = *(const float2*)(xp + 16);
            const float2 x2 = *(const float2*)(xp + 32);
            const float2 x3 = *(const float2*)(xp + 48);
            int code = 0;
#pragma unroll
            for (int r = 0; r < NPROJ; r++) {
                float L0 = x0.x * pr[r][0].x + x0.y * pr[r][0].y;  // leaf j
                float L1 = x1.x * pr[r][1].x + x1.y * pr[r][1].y;  // leaf j+8
                float L2 = x2.x * pr[r][2].x + x2.y * pr[r][2].y;  // leaf j+16
                float L3 = x3.x * pr[r][3].x + x3.y * pr[r][3].y;  // leaf j+24
                float b0 = L0 + L2;            // stage off=16
                float b1 = L1 + L3;            // stage off=16
                float c  = b0 + b1;            // stage off=8
                c += __shfl_xor_sync(0xffffffffu, c, 4);
                c += __shfl_xor_sync(0xffffffffu, c, 2);
                c += __shfl_xor_sync(0xffffffffu, c, 1);
                code |= (c > 0.0f ? 1 : 0) << r;
            }
            if (j == 0)
                g_hash[which][row] = (unsigned char)(code ^ (code >> 1));
        }
    }
}

// ---------------------------------------------------------------------------
// stable counting sort (q and k fused: grid 64)
// ---------------------------------------------------------------------------
__global__ void sort_kernel() {
    __shared__ unsigned char  h[NSEQ];
    __shared__ unsigned short seg[NSEG * ST];
    __shared__ int base[NBUCK];
    __shared__ int tot[NBUCK];
    const int which = blockIdx.x >> 5;
    const int bh = blockIdx.x & 31;
    const int t = threadIdx.x;
    const unsigned char* hp = g_hash[which] + bh * NSEQ;
    int* op = g_idx[which] + bh * NSEQ;
    for (int i = t; i < NSEQ; i += NSEG) h[i] = hp[i];
    for (int i = t; i < NSEG * ST; i += NSEG) seg[i] = 0;
    __syncthreads();
    {
        unsigned short* row = seg + t * ST;
        const int b0 = t * SEGLEN;
        for (int k2 = 0; k2 < SEGLEN; k2++) row[h[b0 + k2]]++;
    }
    __syncthreads();
    {
        int run = 0;
        for (int s = 0; s < NSEG; s++) {
            int c = seg[s * ST + t];
            seg[s * ST + t] = (unsigned short)run;
            run += c;
        }
        tot[t] = run;
    }
    __syncthreads();
    if (t == 0) {
        int run = 0;
        for (int vv = 0; vv < NBUCK; vv++) { base[vv] = run; run += tot[vv]; }
    }
    __syncthreads();
    {
        unsigned short* row = seg + t * ST;
        const int b0 = t * SEGLEN;
        for (int k2 = 0; k2 < SEGLEN; k2++) {
            int i = b0 + k2;
            int vv = h[i];
            op[base[vv] + row[vv]] = i;
            row[vv]++;
        }
    }
}

// ---------------------------------------------------------------------------
// fused attention: grid (64 q-halves, 32 bh), 256 threads (8 warps x 16 rows)
// Q fp16 (scaled by 0.125*log2e); K fp16; V fp16 (single).
// softmax in log2 domain: p = ex2(S + bias') with bias' pre-scaled by log2e.
// ---------------------------------------------------------------------------
__global__ __launch_bounds__(256, 2)
void attn_kernel(const float* __restrict__ q, const float* __restrict__ k,
                 const float* __restrict__ v, const int* __restrict__ sampled,
                 float* __restrict__ out) {
    __shared__ __align__(128) char KsmB[64 * 128];
    __shared__ __align__(128) char VsmB[64 * 128];
    __shared__ float addv[64];

    const int tid  = threadIdx.x;
    const int w    = tid >> 5;
    const int lane = tid & 31;
    const int qhalf = blockIdx.x;
    const int qb    = qhalf >> 1;
    const int bh    = blockIdx.y;
    const size_t bhBase = (size_t)bh * NSEQ;
    const int* qidx = g_idx[0] + bhBase;
    const int* kidx = g_idx[1] + bhBase;
    const int* smp  = sampled + bh * 256;

    const uint32_t Ksm = smem_u32(KsmB);
    const uint32_t Vsm = smem_u32(VsmB);

    // ---- Q fragments straight from gmem (single fp16, scaled) ----
    const int r0 = 16 * w + (lane >> 2);
    const int qrow0 = qidx[qhalf * 128 + r0];
    const int qrow1 = qidx[qhalf * 128 + r0 + 8];
    const float* q0p = q + (bhBase + qrow0) * DIM;
    const float* q1p = q + (bhBase + qrow1) * DIM;
    const float qsc = 0.125f * LOG2E;

    uint32_t qh[4][4];
#pragma unroll
    for (int s = 0; s < 4; s++) {
        const int d = 16 * s + (lane & 3) * 2;
        float2 f00 = *(const float2*)(q0p + d);
        float2 f10 = *(const float2*)(q1p + d);
        float2 f01 = *(const float2*)(q0p + d + 8);
        float2 f11 = *(const float2*)(q1p + d + 8);
        half2 h;
        h = __floats2half2_rn(f00.x * qsc, f00.y * qsc); qh[s][0] = *(uint32_t*)&h;
        h = __floats2half2_rn(f10.x * qsc, f10.y * qsc); qh[s][1] = *(uint32_t*)&h;
        h = __floats2half2_rn(f01.x * qsc, f01.y * qsc); qh[s][2] = *(uint32_t*)&h;
        h = __floats2half2_rn(f11.x * qsc, f11.y * qsc); qh[s][3] = *(uint32_t*)&h;
    }

    float O[8][4];
#pragma unroll
    for (int g = 0; g < 8; g++)
#pragma unroll
        for (int e = 0; e < 4; e++) O[g][e] = 0.0f;
    float lsum0 = 0.0f, lsum1 = 0.0f;

#pragma unroll 1
    for (int c = 0; c < 8; c++) {
        if (c) __syncthreads();
        // ---- gather + convert 64 (key,value) rows ----
        {
            const int j   = tid >> 2;       // key row 0..63
            const int sub = tid & 3;        // dim quarter
            const int kk  = c * 64 + j;
            int srow; float ad;
            if (kk < 256) { srow = qb * 256 + kk; ad = -M_FIX * LOG2E; }
            else {
                int sj = smp[kk - 256];
                srow = sj;
                ad = ((sj >> 8) == qb) ? BIGNEG : ((LOG32 - M_FIX) * LOG2E);
            }
            if (sub == 0) addv[j] = ad;
            const int krow = kidx[srow];
            const float4* ks = (const float4*)(k + (bhBase + krow) * DIM) + sub * 4;
            const float4* vs = (const float4*)(v + (bhBase + krow) * DIM) + sub * 4;
            __half kh16[16], vh16[16];
#pragma unroll
            for (int u = 0; u < 4; u++) {
                float4 f = ks[u];
                kh16[4 * u + 0] = __float2half_rn(f.x);
                kh16[4 * u + 1] = __float2half_rn(f.y);
                kh16[4 * u + 2] = __float2half_rn(f.z);
                kh16[4 * u + 3] = __float2half_rn(f.w);
                float4 g4 = vs[u];
                vh16[4 * u + 0] = __float2half_rn(g4.x);
                vh16[4 * u + 1] = __float2half_rn(g4.y);
                vh16[4 * u + 2] = __float2half_rn(g4.z);
                vh16[4 * u + 3] = __float2half_rn(g4.w);
            }
            const uint32_t o0 = swz((uint32_t)(j * 128 + sub * 32));
            const uint32_t o1 = swz((uint32_t)(j * 128 + sub * 32 + 16));
            *(uint4*)(KsmB + o0) = ((uint4*)kh16)[0];
            *(uint4*)(KsmB + o1) = ((uint4*)kh16)[1];
            *(uint4*)(VsmB + o0) = ((uint4*)vh16)[0];
            *(uint4*)(VsmB + o1) = ((uint4*)vh16)[1];
        }
        __syncthreads();

        // ---- S = Q . K^T  (per-warp 16x64, fp32 frags, log2 domain) ----
        float S[8][4];
#pragma unroll
        for (int g = 0; g < 8; g++)
#pragma unroll
            for (int e = 0; e < 4; e++) S[g][e] = 0.0f;

#pragma unroll
        for (int g = 0; g < 8; g++) {
            uint32_t kb[8];
            const uint32_t key = 8u * g + (lane & 7);
            const uint32_t dv  = ((uint32_t)(lane >> 3) & 3u) * 8u;
            ldsm4(kb,     Ksm + swz(key * 128 + dv * 2));
            ldsm4(kb + 4, Ksm + swz(key * 128 + (32 + dv) * 2));
#pragma unroll
            for (int s = 0; s < 4; s++) mma16816(S[g], qh[s], kb[2 * s], kb[2 * s + 1]);
        }

        // ---- softmax (fixed shift, log2) -> P fp16 fragments ----
        uint32_t P01[8], P23[8];
#pragma unroll
        for (int g = 0; g < 8; g++) {
            const int n0 = 8 * g + (lane & 3) * 2;
            const float av0 = addv[n0], av1 = addv[n0 + 1];
            float e0 = ex2f(S[g][0] + av0);
            float e1 = ex2f(S[g][1] + av1);
            float e2 = ex2f(S[g][2] + av0);
            float e3 = ex2f(S[g][3] + av1);
            lsum0 += e0 + e1;
            lsum1 += e2 + e3;
            half2 h01 = __floats2half2_rn(e0, e1);
            half2 h23 = __floats2half2_rn(e2, e3);
            P01[g] = *(uint32_t*)&h01;
            P23[g] = *(uint32_t*)&h23;
        }

        // ---- O += P . V ----
#pragma unroll
        for (int j = 0; j < 4; j++) {             // key steps of 16
            uint32_t A[4] = {P01[2 * j], P23[2 * j], P01[2 * j + 1], P23[2 * j + 1]};
            const uint32_t key = 16u * j + ((uint32_t)lane & 15u);
            const uint32_t dof = ((uint32_t)(lane >> 4) & 1u) * 8u;
#pragma unroll
            for (int dg = 0; dg < 4; dg++) {      // dim groups of 16
                uint32_t vb[4];
                ldsm4t(vb, Vsm + swz(key * 128 + (16u * dg + dof) * 2));
                mma16816(O[2 * dg],     A, vb[0], vb[1]);
                mma16816(O[2 * dg + 1], A, vb[2], vb[3]);
            }
        }
    }

    // ---- epilogue: row sums across the quad, normalize, store ----
    lsum0 += __shfl_xor_sync(0xffffffffu, lsum0, 1);
    lsum0 += __shfl_xor_sync(0xffffffffu, lsum0, 2);
    lsum1 += __shfl_xor_sync(0xffffffffu, lsum1, 1);
    lsum1 += __shfl_xor_sync(0xffffffffu, lsum1, 2);
    const float inv0 = 1.0f / lsum0;
    const float inv1 = 1.0f / lsum1;

    float* o0p = out + (bhBase + qrow0) * DIM;
    float* o1p = out + (bhBase + qrow1) * DIM;
#pragma unroll
    for (int g = 0; g < 8; g++) {
        const int n0 = 8 * g + (lane & 3) * 2;
        float2 a = {O[g][0] * inv0, O[g][1] * inv0};
        float2 b = {O[g][2] * inv1, O[g][3] * inv1};
        *(float2*)(o0p + n0) = a;
        *(float2*)(o1p + n0) = b;
    }
}

// ---------------------------------------------------------------------------
extern "C" void kernel_launch(void* const* d_in, const int* in_sizes, int n_in,
                              void* d_out, int out_size) {
    (void)in_sizes; (void)n_in; (void)out_size;
    const float* q    = (const float*)d_in[0];
    const float* k    = (const float*)d_in[1];
    const float* v    = (const float*)d_in[2];
    const float* proj = (const float*)d_in[3];
    const int*   smp  = (const int*)d_in[4];
    float* out = (float*)d_out;

    hash_kernel<<<512, 256>>>(q, k, proj);
    sort_kernel<<<64, 128>>>();
    attn_kernel<<<dim3(64, 32), 256>>>(q, k, v, smp, out);
}

// round 9
// speedup vs baseline: 5.5189x; 1.2170x over previous
#include <cuda_runtime.h>
#include <cuda_fp16.h>
#include <cstdint>

// ---------------------------------------------------------------------------
// HyperAttention on GB300 (sm_103 baseline PTX): mma.sync m16n8k16 flash
// attention with fixed-shift softmax (log2 domain).  B=2,H=16,N=8192,D=64.
// CTA = 256 sorted queries x 512 keys (8 chunks of 64), double-buffered.
// ---------------------------------------------------------------------------

#define BH      32
#define NSEQ    8192
#define DIM     64
#define NPROJ   7
#define NBUCK   128
#define NSEG    128
#define SEGLEN  64
#define ST      130
#define LOG32   3.4657359027997265f
#define BIGNEG  (-1e30f)
#define M_FIX   6.0f
#define LOG2E   1.4426950408889634f

__device__ unsigned char g_hash[2][BH * NSEQ];
__device__ int           g_idx[2][BH * NSEQ];   // [0]=q_idx, [1]=k_idx

// ===================== helpers =============================================
__device__ __forceinline__ uint32_t smem_u32(const void* p) {
    uint32_t a;
    asm("{ .reg .u64 t; cvta.to.shared.u64 t, %1; cvt.u32.u64 %0, t; }"
        : "=r"(a) : "l"(p));
    return a;
}
__device__ __forceinline__ uint32_t swz(uint32_t o) { return o ^ ((o >> 3) & 0x70); }

__device__ __forceinline__ float ex2f(float x) {
    float y; asm("ex2.approx.ftz.f32 %0, %1;" : "=f"(y) : "f"(x)); return y;
}
__device__ __forceinline__ void mma16816(float* c, const uint32_t* a,
                                         uint32_t b0, uint32_t b1) {
    asm volatile(
        "mma.sync.aligned.m16n8k16.row.col.f32.f16.f16.f32 "
        "{%0,%1,%2,%3}, {%4,%5,%6,%7}, {%8,%9}, {%0,%1,%2,%3};"
        : "+f"(c[0]), "+f"(c[1]), "+f"(c[2]), "+f"(c[3])
        : "r"(a[0]), "r"(a[1]), "r"(a[2]), "r"(a[3]), "r"(b0), "r"(b1));
}
__device__ __forceinline__ void ldsm4(uint32_t* r, uint32_t addr) {
    asm volatile("ldmatrix.sync.aligned.m8n8.x4.shared.b16 {%0,%1,%2,%3}, [%4];"
        : "=r"(r[0]), "=r"(r[1]), "=r"(r[2]), "=r"(r[3]) : "r"(addr));
}
__device__ __forceinline__ void ldsm4t(uint32_t* r, uint32_t addr) {
    asm volatile("ldmatrix.sync.aligned.m8n8.x4.trans.shared.b16 {%0,%1,%2,%3}, [%4];"
        : "=r"(r[0]), "=r"(r[1]), "=r"(r[2]), "=r"(r[3]) : "r"(addr));
}

// ---------------------------------------------------------------------------
// LSH hash: thread-per-row, smem-staged tiles for coalesced gmem access.
// Reduction arithmetic BIT-EXACT copy of the validated round-7 tree.
// ---------------------------------------------------------------------------
__global__ __launch_bounds__(256)
void hash_kernel(const float* __restrict__ q,
                 const float* __restrict__ k,
                 const float* __restrict__ proj) {
    __shared__ float pjs[NPROJ][DIM];       // pjs[r][d] = proj[d*NPROJ + r]
    __shared__ float4 xs4[256 * 16];        // 256 rows x 16 granules (64KB)
    const int t = threadIdx.x;
    for (int i = t; i < DIM * NPROJ; i += 256)
        pjs[i % NPROJ][i / NPROJ] = proj[i];

    const int rowg = blockIdx.x * 256 + t;  // this thread's row

#pragma unroll 1
    for (int which = 0; which < 2; which++) {
        const float4* src = (const float4*)(which ? k : q);
        __syncthreads();   // protect xs4 reuse (and pjs on first pass)
        // stage 256 rows coalesced, granule-swizzled
        for (int i = t; i < 4096; i += 256) {
            const int row = i >> 4, u = i & 15;
            xs4[row * 16 + (u ^ (row & 7))] = src[(size_t)blockIdx.x * 4096 + i];
        }
        __syncthreads();

        float xr[DIM];
#pragma unroll
        for (int u = 0; u < 16; u++) {
            float4 f = xs4[t * 16 + (u ^ (t & 7))];
            xr[4 * u] = f.x; xr[4 * u + 1] = f.y;
            xr[4 * u + 2] = f.z; xr[4 * u + 3] = f.w;
        }
        int code = 0;
#pragma unroll 1
        for (int r = 0; r < NPROJ; r++) {
            float a[32];
#pragma unroll
            for (int l = 0; l < 16; l++) {
                float4 p4 = *(const float4*)&pjs[r][4 * l];
                a[2 * l]     = xr[4 * l]     * p4.x + xr[4 * l + 1] * p4.y;
                a[2 * l + 1] = xr[4 * l + 2] * p4.z + xr[4 * l + 3] * p4.w;
            }
#pragma unroll
            for (int off = 16; off > 0; off >>= 1)
#pragma unroll
                for (int i = 0; i < 32; i++)
                    if (i < off) a[i] += a[i + off];
            code |= (a[0] > 0.0f ? 1 : 0) << r;
        }
        g_hash[which][rowg] = (unsigned char)(code ^ (code >> 1));
    }
}

// ---------------------------------------------------------------------------
// stable counting sort (q and k fused: grid 64)
// ---------------------------------------------------------------------------
__global__ void sort_kernel() {
    __shared__ unsigned char  h[NSEQ];
    __shared__ unsigned short seg[NSEG * ST];
    __shared__ int base[NBUCK];
    __shared__ int tot[NBUCK];
    const int which = blockIdx.x >> 5;
    const int bh = blockIdx.x & 31;
    const int t = threadIdx.x;
    const unsigned char* hp = g_hash[which] + bh * NSEQ;
    int* op = g_idx[which] + bh * NSEQ;
    for (int i = t; i < NSEQ; i += NSEG) h[i] = hp[i];
    for (int i = t; i < NSEG * ST; i += NSEG) seg[i] = 0;
    __syncthreads();
    {
        unsigned short* row = seg + t * ST;
        const int b0 = t * SEGLEN;
        for (int k2 = 0; k2 < SEGLEN; k2++) row[h[b0 + k2]]++;
    }
    __syncthreads();
    {
        int run = 0;
        for (int s = 0; s < NSEG; s++) {
            int c = seg[s * ST + t];
            seg[s * ST + t] = (unsigned short)run;
            run += c;
        }
        tot[t] = run;
    }
    __syncthreads();
    if (t == 0) {
        int run = 0;
        for (int vv = 0; vv < NBUCK; vv++) { base[vv] = run; run += tot[vv]; }
    }
    __syncthreads();
    {
        unsigned short* row = seg + t * ST;
        const int b0 = t * SEGLEN;
        for (int k2 = 0; k2 < SEGLEN; k2++) {
            int i = b0 + k2;
            int vv = h[i];
            op[base[vv] + row[vv]] = i;
            row[vv]++;
        }
    }
}

// ---------------------------------------------------------------------------
// fused attention: grid (32 qb, 32 bh), 512 threads (16 warps x 16 q-rows).
// Double-buffered K/V tiles; chunk c+1 gather LDGs issued before chunk c MMA.
// Q fp16 (scaled 0.125*log2e); K fp16; V fp16; softmax log2-domain fixed shift.
// ---------------------------------------------------------------------------
__global__ __launch_bounds__(512, 1)
void attn_kernel(const float* __restrict__ q, const float* __restrict__ k,
                 const float* __restrict__ v, const int* __restrict__ sampled,
                 float* __restrict__ out) {
    __shared__ __align__(128) char KsmB[2 * 8192];
    __shared__ __align__(128) char VsmB[2 * 8192];
    __shared__ float addv[2][64];

    const int tid  = threadIdx.x;
    const int w    = tid >> 5;          // 0..15
    const int lane = tid & 31;
    const int qb   = blockIdx.x;
    const int bh   = blockIdx.y;
    const size_t bhBase = (size_t)bh * NSEQ;
    const int* qidx = g_idx[0] + bhBase;
    const int* kidx = g_idx[1] + bhBase;
    const int* smp  = sampled + bh * 256;

    const uint32_t Ksm = smem_u32(KsmB);
    const uint32_t Vsm = smem_u32(VsmB);

    // ---- Q fragments straight from gmem (fp16, scaled) ----
    const int r0 = 16 * w + (lane >> 2);          // 0..255
    const int qrow0 = qidx[qb * 256 + r0];
    const int qrow1 = qidx[qb * 256 + r0 + 8];
    const float* q0p = q + (bhBase + qrow0) * DIM;
    const float* q1p = q + (bhBase + qrow1) * DIM;
    const float qsc = 0.125f * LOG2E;

    uint32_t qh[4][4];
#pragma unroll
    for (int s = 0; s < 4; s++) {
        const int d = 16 * s + (lane & 3) * 2;
        float2 f00 = *(const float2*)(q0p + d);
        float2 f10 = *(const float2*)(q1p + d);
        float2 f01 = *(const float2*)(q0p + d + 8);
        float2 f11 = *(const float2*)(q1p + d + 8);
        half2 h;
        h = __floats2half2_rn(f00.x * qsc, f00.y * qsc); qh[s][0] = *(uint32_t*)&h;
        h = __floats2half2_rn(f10.x * qsc, f10.y * qsc); qh[s][1] = *(uint32_t*)&h;
        h = __floats2half2_rn(f01.x * qsc, f01.y * qsc); qh[s][2] = *(uint32_t*)&h;
        h = __floats2half2_rn(f11.x * qsc, f11.y * qsc); qh[s][3] = *(uint32_t*)&h;
    }

    // ---- gather lane mapping: 8 threads per key row, 32B per tensor ----
    const int j   = tid >> 3;          // key row 0..63
    const int sub = tid & 7;           // dim octet (8 floats)

    float O[8][4];
#pragma unroll
    for (int g = 0; g < 8; g++)
#pragma unroll
        for (int e = 0; e < 4; e++) O[g][e] = 0.0f;
    float lsum0 = 0.0f, lsum1 = 0.0f;

    float4 kA, kB, vA, vB; float ad;

    // prologue: gather + convert chunk 0 into buffer 0
    {
        const int srow = qb * 256 + j;
        ad = -M_FIX * LOG2E;
        const int krow = kidx[srow];
        const float4* ks = (const float4*)(k + (bhBase + krow) * DIM + sub * 8);
        const float4* vs = (const float4*)(v + (bhBase + krow) * DIM + sub * 8);
        kA = ks[0]; kB = ks[1]; vA = vs[0]; vB = vs[1];
        const uint32_t o0 = swz((uint32_t)(j * 128 + sub * 16));
        half2 h0 = __floats2half2_rn(kA.x, kA.y), h1 = __floats2half2_rn(kA.z, kA.w);
        half2 h2 = __floats2half2_rn(kB.x, kB.y), h3 = __floats2half2_rn(kB.z, kB.w);
        uint4 pk = {*(uint32_t*)&h0, *(uint32_t*)&h1, *(uint32_t*)&h2, *(uint32_t*)&h3};
        *(uint4*)(KsmB + o0) = pk;
        h0 = __floats2half2_rn(vA.x, vA.y); h1 = __floats2half2_rn(vA.z, vA.w);
        h2 = __floats2half2_rn(vB.x, vB.y); h3 = __floats2half2_rn(vB.z, vB.w);
        uint4 pv = {*(uint32_t*)&h0, *(uint32_t*)&h1, *(uint32_t*)&h2, *(uint32_t*)&h3};
        *(uint4*)(VsmB + o0) = pv;
        if (sub == 0) addv[0][j] = ad;
    }
    __syncthreads();

#pragma unroll 1
    for (int c = 0; c < 8; c++) {
        // ---- issue chunk c+1 gather LDGs early (latency hidden by MMA) ----
        if (c < 7) {
            const int kk = (c + 1) * 64 + j;
            int srow;
            if (kk < 256) { srow = qb * 256 + kk; ad = -M_FIX * LOG2E; }
            else {
                int sj = smp[kk - 256];
                srow = sj;
                ad = ((sj >> 8) == qb) ? BIGNEG : ((LOG32 - M_FIX) * LOG2E);
            }
            const int krow = kidx[srow];
            const float4* ks = (const float4*)(k + (bhBase + krow) * DIM + sub * 8);
            const float4* vs = (const float4*)(v + (bhBase + krow) * DIM + sub * 8);
            kA = ks[0]; kB = ks[1]; vA = vs[0]; vB = vs[1];
        }

        const uint32_t Kb = Ksm + (uint32_t)(c & 1) * 8192;
        const uint32_t Vb = Vsm + (uint32_t)(c & 1) * 8192;
        const float* av = addv[c & 1];

        // ---- S = Q.K^T then fused softmax -> P fp16 fragments ----
        uint32_t P01[8], P23[8];
#pragma unroll
        for (int g = 0; g < 8; g++) {
            uint32_t kb[8];
            const uint32_t key = 8u * g + (lane & 7);
            const uint32_t dv  = ((uint32_t)(lane >> 3) & 3u) * 8u;
            ldsm4(kb,     Kb + swz(key * 128 + dv * 2));
            ldsm4(kb + 4, Kb + swz(key * 128 + (32 + dv) * 2));
            float S[4] = {0.0f, 0.0f, 0.0f, 0.0f};
#pragma unroll
            for (int s = 0; s < 4; s++) mma16816(S, qh[s], kb[2 * s], kb[2 * s + 1]);
            const int n0 = 8 * g + (lane & 3) * 2;
            const float av0 = av[n0], av1 = av[n0 + 1];
            float e0 = ex2f(S[0] + av0);
            float e1 = ex2f(S[1] + av1);
            float e2 = ex2f(S[2] + av0);
            float e3 = ex2f(S[3] + av1);
            lsum0 += e0 + e1;
            lsum1 += e2 + e3;
            half2 h01 = __floats2half2_rn(e0, e1);
            half2 h23 = __floats2half2_rn(e2, e3);
            P01[g] = *(uint32_t*)&h01;
            P23[g] = *(uint32_t*)&h23;
        }

        // ---- O += P . V ----
#pragma unroll
        for (int jj = 0; jj < 4; jj++) {          // key steps of 16
            uint32_t A[4] = {P01[2 * jj], P23[2 * jj], P01[2 * jj + 1], P23[2 * jj + 1]};
            const uint32_t key = 16u * jj + ((uint32_t)lane & 15u);
            const uint32_t dof = ((uint32_t)(lane >> 4) & 1u) * 8u;
#pragma unroll
            for (int dg = 0; dg < 4; dg++) {      // dim groups of 16
                uint32_t vb[4];
                ldsm4t(vb, Vb + swz(key * 128 + (16u * dg + dof) * 2));
                mma16816(O[2 * dg],     A, vb[0], vb[1]);
                mma16816(O[2 * dg + 1], A, vb[2], vb[3]);
            }
        }

        // ---- convert + store chunk c+1 into the other buffer ----
        if (c < 7) {
            char* Kd = KsmB + ((c + 1) & 1) * 8192;
            char* Vd = VsmB + ((c + 1) & 1) * 8192;
            const uint32_t o0 = swz((uint32_t)(j * 128 + sub * 16));
            half2 h0 = __floats2half2_rn(kA.x, kA.y), h1 = __floats2half2_rn(kA.z, kA.w);
            half2 h2 = __floats2half2_rn(kB.x, kB.y), h3 = __floats2half2_rn(kB.z, kB.w);
            uint4 pk = {*(uint32_t*)&h0, *(uint32_t*)&h1, *(uint32_t*)&h2, *(uint32_t*)&h3};
            *(uint4*)(Kd + o0) = pk;
            h0 = __floats2half2_rn(vA.x, vA.y); h1 = __floats2half2_rn(vA.z, vA.w);
            h2 = __floats2half2_rn(vB.x, vB.y); h3 = __floats2half2_rn(vB.z, vB.w);
            uint4 pv = {*(uint32_t*)&h0, *(uint32_t*)&h1, *(uint32_t*)&h2, *(uint32_t*)&h3};
            *(uint4*)(Vd + o0) = pv;
            if (sub == 0) addv[(c + 1) & 1][j] = ad;
        }
        __syncthreads();
    }

    // ---- epilogue: row sums across the quad, normalize, store ----
    lsum0 += __shfl_xor_sync(0xffffffffu, lsum0, 1);
    lsum0 += __shfl_xor_sync(0xffffffffu, lsum0, 2);
    lsum1 += __shfl_xor_sync(0xffffffffu, lsum1, 1);
    lsum1 += __shfl_xor_sync(0xffffffffu, lsum1, 2);
    const float inv0 = 1.0f / lsum0;
    const float inv1 = 1.0f / lsum1;

    float* o0p = out + (bhBase + qrow0) * DIM;
    float* o1p = out + (bhBase + qrow1) * DIM;
#pragma unroll
    for (int g = 0; g < 8; g++) {
        const int n0 = 8 * g + (lane & 3) * 2;
        float2 a = {O[g][0] * inv0, O[g][1] * inv0};
        float2 b = {O[g][2] * inv1, O[g][3] * inv1};
        *(float2*)(o0p + n0) = a;
        *(float2*)(o1p + n0) = b;
    }
}

// ---------------------------------------------------------------------------
extern "C" void kernel_launch(void* const* d_in, const int* in_sizes, int n_in,
                              void* d_out, int out_size) {
    (void)in_sizes; (void)n_in; (void)out_size;
    const float* q    = (const float*)d_in[0];
    const float* k    = (const float*)d_in[1];
    const float* v    = (const float*)d_in[2];
    const float* proj = (const float*)d_in[3];
    const int*   smp  = (const int*)d_in[4];
    float* out = (float*)d_out;

    hash_kernel<<<1024, 256>>>(q, k, proj);
    sort_kernel<<<64, 128>>>();
    attn_kernel<<<dim3(32, 32), 512>>>(q, k, v, smp, out);
}

// round 10
// speedup vs baseline: 6.0636x; 1.0987x over previous
#include <cuda_runtime.h>
#include <cuda_fp16.h>
#include <cstdint>

// ---------------------------------------------------------------------------
// HyperAttention on GB300 (sm_103 baseline PTX): mma.sync m16n8k16 flash
// attention, fixed-shift softmax (log2 domain).  B=2,H=16,N=8192,D=64.
// attn CTA = 256 queries x 512 keys, 8 warps, 32 q-rows per warp.
// ---------------------------------------------------------------------------

#define BH      32
#define NSEQ    8192
#define DIM     64
#define NPROJ   7
#define NBUCK   128
#define NSEG    128
#define SEGLEN  64
#define ST      130
#define LOG32   3.4657359027997265f
#define BIGNEG  (-1e30f)
#define M_FIX   6.0f
#define LOG2E   1.4426950408889634f

__device__ unsigned char g_hash[2][BH * NSEQ];
__device__ int           g_idx[2][BH * NSEQ];   // [0]=q_idx, [1]=k_idx

// ===================== helpers =============================================
__device__ __forceinline__ uint32_t smem_u32(const void* p) {
    uint32_t a;
    asm("{ .reg .u64 t; cvta.to.shared.u64 t, %1; cvt.u32.u64 %0, t; }"
        : "=r"(a) : "l"(p));
    return a;
}
__device__ __forceinline__ uint32_t swz(uint32_t o) { return o ^ ((o >> 3) & 0x70); }

__device__ __forceinline__ float ex2f(float x) {
    float y; asm("ex2.approx.ftz.f32 %0, %1;" : "=f"(y) : "f"(x)); return y;
}
__device__ __forceinline__ void cpasync16(uint32_t d, const void* s) {
    asm volatile("cp.async.cg.shared.global [%0], [%1], 16;" :: "r"(d), "l"(s));
}
__device__ __forceinline__ void cpasync_wait() {
    asm volatile("cp.async.commit_group;\n\tcp.async.wait_group 0;" ::: "memory");
}
__device__ __forceinline__ void mma16816(float* c, const uint32_t* a,
                                         uint32_t b0, uint32_t b1) {
    asm volatile(
        "mma.sync.aligned.m16n8k16.row.col.f32.f16.f16.f32 "
        "{%0,%1,%2,%3}, {%4,%5,%6,%7}, {%8,%9}, {%0,%1,%2,%3};"
        : "+f"(c[0]), "+f"(c[1]), "+f"(c[2]), "+f"(c[3])
        : "r"(a[0]), "r"(a[1]), "r"(a[2]), "r"(a[3]), "r"(b0), "r"(b1));
}
__device__ __forceinline__ void ldsm4(uint32_t* r, uint32_t addr) {
    asm volatile("ldmatrix.sync.aligned.m8n8.x4.shared.b16 {%0,%1,%2,%3}, [%4];"
        : "=r"(r[0]), "=r"(r[1]), "=r"(r[2]), "=r"(r[3]) : "r"(addr));
}
__device__ __forceinline__ void ldsm4t(uint32_t* r, uint32_t addr) {
    asm volatile("ldmatrix.sync.aligned.m8n8.x4.trans.shared.b16 {%0,%1,%2,%3}, [%4];"
        : "=r"(r[0]), "=r"(r[1]), "=r"(r[2]), "=r"(r[3]) : "r"(addr));
}

// ---------------------------------------------------------------------------
// LSH hash: cp.async-staged 128-row q-tile + 128-row k-tile per CTA.
// Threads 0-127 hash q rows, threads 128-255 hash k rows concurrently.
// Reduction arithmetic BIT-EXACT copy of the validated tree.
// ---------------------------------------------------------------------------
__global__ __launch_bounds__(256)
void hash_kernel(const float* __restrict__ q,
                 const float* __restrict__ k,
                 const float* __restrict__ proj) {
    __shared__ float  pjs[NPROJ][DIM];       // pjs[r][d] = proj[d*NPROJ + r]
    __shared__ float4 buf[2][128 * 16];      // q-tile, k-tile (64KB)
    const int t = threadIdx.x;
    for (int i = t; i < DIM * NPROJ; i += 256)
        pjs[i % NPROJ][i / NPROJ] = proj[i];

    // stage both tiles with cp.async (coalesced, granule-swizzled dest)
    const float4* qs = (const float4*)q + (size_t)blockIdx.x * 2048;
    const float4* ks = (const float4*)k + (size_t)blockIdx.x * 2048;
    const uint32_t b0 = smem_u32(&buf[0][0]);
    const uint32_t b1 = smem_u32(&buf[1][0]);
    for (int i = t; i < 2048; i += 256) {
        const int row = i >> 4, u = i & 15;
        const uint32_t off = (uint32_t)(row * 16 + (u ^ (row & 7))) * 16u;
        cpasync16(b0 + off, qs + i);
        cpasync16(b1 + off, ks + i);
    }
    cpasync_wait();
    __syncthreads();

    const int which = t >> 7;           // 0: q rows, 1: k rows
    const int r0 = t & 127;
    const float4* mybuf = buf[which];

    float xr[DIM];
#pragma unroll
    for (int u = 0; u < 16; u++) {
        float4 f = mybuf[r0 * 16 + (u ^ (r0 & 7))];
        xr[4 * u] = f.x; xr[4 * u + 1] = f.y;
        xr[4 * u + 2] = f.z; xr[4 * u + 3] = f.w;
    }
    int code = 0;
#pragma unroll 1
    for (int r = 0; r < NPROJ; r++) {
        float a[32];
#pragma unroll
        for (int l = 0; l < 16; l++) {
            float4 p4 = *(const float4*)&pjs[r][4 * l];
            a[2 * l]     = xr[4 * l]     * p4.x + xr[4 * l + 1] * p4.y;
            a[2 * l + 1] = xr[4 * l + 2] * p4.z + xr[4 * l + 3] * p4.w;
        }
#pragma unroll
        for (int off = 16; off > 0; off >>= 1)
#pragma unroll
            for (int i = 0; i < 32; i++)
                if (i < off) a[i] += a[i + off];
        code |= (a[0] > 0.0f ? 1 : 0) << r;
    }
    g_hash[which][blockIdx.x * 128 + r0] = (unsigned char)(code ^ (code >> 1));
}

// ---------------------------------------------------------------------------
// stable counting sort (q and k fused: grid 64)
// ---------------------------------------------------------------------------
__global__ void sort_kernel() {
    __shared__ unsigned char  h[NSEQ];
    __shared__ unsigned short seg[NSEG * ST];
    __shared__ int base[NBUCK];
    __shared__ int tot[NBUCK];
    const int which = blockIdx.x >> 5;
    const int bh = blockIdx.x & 31;
    const int t = threadIdx.x;
    const unsigned char* hp = g_hash[which] + bh * NSEQ;
    int* op = g_idx[which] + bh * NSEQ;
    for (int i = t; i < NSEQ; i += NSEG) h[i] = hp[i];
    for (int i = t; i < NSEG * ST; i += NSEG) seg[i] = 0;
    __syncthreads();
    {
        unsigned short* row = seg + t * ST;
        const int b0 = t * SEGLEN;
        for (int k2 = 0; k2 < SEGLEN; k2++) row[h[b0 + k2]]++;
    }
    __syncthreads();
    {
        int run = 0;
        for (int s = 0; s < NSEG; s++) {
            int c = seg[s * ST + t];
            seg[s * ST + t] = (unsigned short)run;
            run += c;
        }
        tot[t] = run;
    }
    __syncthreads();
    if (t == 0) {
        int run = 0;
        for (int vv = 0; vv < NBUCK; vv++) { base[vv] = run; run += tot[vv]; }
    }
    __syncthreads();
    {
        unsigned short* row = seg + t * ST;
        const int b0 = t * SEGLEN;
        for (int k2 = 0; k2 < SEGLEN; k2++) {
            int i = b0 + k2;
            int vv = h[i];
            op[base[vv] + row[vv]] = i;
            row[vv]++;
        }
    }
}

// ---------------------------------------------------------------------------
// fused attention: grid (32 qb, 32 bh), 256 threads (8 warps x 32 q-rows).
// Each warp computes two m16 tiles sharing one set of K/V fragments.
// Double-buffered K/V smem; chunk c+1 LDGs issued before chunk c MMAs.
// ---------------------------------------------------------------------------
__global__ __launch_bounds__(256, 1)
void attn_kernel(const float* __restrict__ q, const float* __restrict__ k,
                 const float* __restrict__ v, const int* __restrict__ sampled,
                 float* __restrict__ out) {
    __shared__ __align__(128) char KsmB[2 * 8192];
    __shared__ __align__(128) char VsmB[2 * 8192];
    __shared__ float addv[2][64];

    const int tid  = threadIdx.x;
    const int w    = tid >> 5;          // 0..7
    const int lane = tid & 31;
    const int qb   = blockIdx.x;
    const int bh   = blockIdx.y;
    const size_t bhBase = (size_t)bh * NSEQ;
    const int* qidx = g_idx[0] + bhBase;
    const int* kidx = g_idx[1] + bhBase;
    const int* smp  = sampled + bh * 256;

    const uint32_t Ksm = smem_u32(KsmB);
    const uint32_t Vsm = smem_u32(VsmB);

    // ---- Q fragments: warp w owns rows [32w, 32w+32): tiles t0, t1 ----
    const int rt = 32 * w + (lane >> 2);
    int qrow[2][2];
    qrow[0][0] = qidx[qb * 256 + rt];
    qrow[0][1] = qidx[qb * 256 + rt + 8];
    qrow[1][0] = qidx[qb * 256 + rt + 16];
    qrow[1][1] = qidx[qb * 256 + rt + 24];
    const float qsc = 0.125f * LOG2E;

    uint32_t qh[2][4][4];
#pragma unroll
    for (int tt = 0; tt < 2; tt++) {
        const float* q0p = q + (bhBase + qrow[tt][0]) * DIM;
        const float* q1p = q + (bhBase + qrow[tt][1]) * DIM;
#pragma unroll
        for (int s = 0; s < 4; s++) {
            const int d = 16 * s + (lane & 3) * 2;
            float2 f00 = *(const float2*)(q0p + d);
            float2 f10 = *(const float2*)(q1p + d);
            float2 f01 = *(const float2*)(q0p + d + 8);
            float2 f11 = *(const float2*)(q1p + d + 8);
            half2 h;
            h = __floats2half2_rn(f00.x * qsc, f00.y * qsc); qh[tt][s][0] = *(uint32_t*)&h;
            h = __floats2half2_rn(f10.x * qsc, f10.y * qsc); qh[tt][s][1] = *(uint32_t*)&h;
            h = __floats2half2_rn(f01.x * qsc, f01.y * qsc); qh[tt][s][2] = *(uint32_t*)&h;
            h = __floats2half2_rn(f11.x * qsc, f11.y * qsc); qh[tt][s][3] = *(uint32_t*)&h;
        }
    }

    // ---- gather lane mapping: 4 threads per key row, 64B per tensor ----
    const int j   = tid >> 2;          // key row 0..63
    const int sub = tid & 3;           // dim quarter (16 floats)

    float O[2][8][4];
#pragma unroll
    for (int tt = 0; tt < 2; tt++)
#pragma unroll
        for (int g = 0; g < 8; g++)
#pragma unroll
            for (int e = 0; e < 4; e++) O[tt][g][e] = 0.0f;
    float lsum[2][2] = {{0.0f, 0.0f}, {0.0f, 0.0f}};

    float4 kR[4], vR[4]; float ad;

    // prologue: gather + convert chunk 0 into buffer 0
    {
        const int srow = qb * 256 + j;
        ad = -M_FIX * LOG2E;
        const int krow = kidx[srow];
        const float4* ks = (const float4*)(k + (bhBase + krow) * DIM + sub * 16);
        const float4* vs = (const float4*)(v + (bhBase + krow) * DIM + sub * 16);
#pragma unroll
        for (int u = 0; u < 4; u++) { kR[u] = ks[u]; vR[u] = vs[u]; }
#pragma unroll
        for (int hf = 0; hf < 2; hf++) {
            const uint32_t o0 = swz((uint32_t)(j * 128 + sub * 32 + hf * 16));
            half2 h0 = __floats2half2_rn(kR[2 * hf].x, kR[2 * hf].y);
            half2 h1 = __floats2half2_rn(kR[2 * hf].z, kR[2 * hf].w);
            half2 h2 = __floats2half2_rn(kR[2 * hf + 1].x, kR[2 * hf + 1].y);
            half2 h3 = __floats2half2_rn(kR[2 * hf + 1].z, kR[2 * hf + 1].w);
            uint4 pk = {*(uint32_t*)&h0, *(uint32_t*)&h1, *(uint32_t*)&h2, *(uint32_t*)&h3};
            *(uint4*)(KsmB + o0) = pk;
            h0 = __floats2half2_rn(vR[2 * hf].x, vR[2 * hf].y);
            h1 = __floats2half2_rn(vR[2 * hf].z, vR[2 * hf].w);
            h2 = __floats2half2_rn(vR[2 * hf + 1].x, vR[2 * hf + 1].y);
            h3 = __floats2half2_rn(vR[2 * hf + 1].z, vR[2 * hf + 1].w);
            uint4 pv = {*(uint32_t*)&h0, *(uint32_t*)&h1, *(uint32_t*)&h2, *(uint32_t*)&h3};
            *(uint4*)(VsmB + o0) = pv;
        }
        if (sub == 0) addv[0][j] = ad;
    }
    __syncthreads();

#pragma unroll 1
    for (int c = 0; c < 8; c++) {
        // ---- issue chunk c+1 gather LDGs early (hidden by MMAs) ----
        if (c < 7) {
            const int kk = (c + 1) * 64 + j;
            int srow;
            if (kk < 256) { srow = qb * 256 + kk; ad = -M_FIX * LOG2E; }
            else {
                int sj = smp[kk - 256];
                srow = sj;
                ad = ((sj >> 8) == qb) ? BIGNEG : ((LOG32 - M_FIX) * LOG2E);
            }
            const int krow = kidx[srow];
            const float4* ks = (const float4*)(k + (bhBase + krow) * DIM + sub * 16);
            const float4* vs = (const float4*)(v + (bhBase + krow) * DIM + sub * 16);
#pragma unroll
            for (int u = 0; u < 4; u++) { kR[u] = ks[u]; vR[u] = vs[u]; }
        }

        const uint32_t Kb = Ksm + (uint32_t)(c & 1) * 8192;
        const uint32_t Vb = Vsm + (uint32_t)(c & 1) * 8192;
        const float* av = addv[c & 1];

        // ---- S = Q.K^T + fused softmax -> P fragments (both tiles) ----
        uint32_t P01[2][8], P23[2][8];
#pragma unroll
        for (int g = 0; g < 8; g++) {
            uint32_t kb[8];
            const uint32_t key = 8u * g + (lane & 7);
            const uint32_t dv  = ((uint32_t)(lane >> 3) & 3u) * 8u;
            ldsm4(kb,     Kb + swz(key * 128 + dv * 2));
            ldsm4(kb + 4, Kb + swz(key * 128 + (32 + dv) * 2));
            const int n0 = 8 * g + (lane & 3) * 2;
            const float av0 = av[n0], av1 = av[n0 + 1];
#pragma unroll
            for (int tt = 0; tt < 2; tt++) {
                float S[4] = {0.0f, 0.0f, 0.0f, 0.0f};
#pragma unroll
                for (int s = 0; s < 4; s++)
                    mma16816(S, qh[tt][s], kb[2 * s], kb[2 * s + 1]);
                float e0 = ex2f(S[0] + av0);
                float e1 = ex2f(S[1] + av1);
                float e2 = ex2f(S[2] + av0);
                float e3 = ex2f(S[3] + av1);
                lsum[tt][0] += e0 + e1;
                lsum[tt][1] += e2 + e3;
                half2 h01 = __floats2half2_rn(e0, e1);
                half2 h23 = __floats2half2_rn(e2, e3);
                P01[tt][g] = *(uint32_t*)&h01;
                P23[tt][g] = *(uint32_t*)&h23;
            }
        }

        // ---- O += P . V  (V fragments shared across both tiles) ----
#pragma unroll
        for (int jj = 0; jj < 4; jj++) {
            const uint32_t key = 16u * jj + ((uint32_t)lane & 15u);
            const uint32_t dof = ((uint32_t)(lane >> 4) & 1u) * 8u;
            uint32_t A0[4] = {P01[0][2 * jj], P23[0][2 * jj],
                              P01[0][2 * jj + 1], P23[0][2 * jj + 1]};
            uint32_t A1[4] = {P01[1][2 * jj], P23[1][2 * jj],
                              P01[1][2 * jj + 1], P23[1][2 * jj + 1]};
#pragma unroll
            for (int dg = 0; dg < 4; dg++) {
                uint32_t vb[4];
                ldsm4t(vb, Vb + swz(key * 128 + (16u * dg + dof) * 2));
                mma16816(O[0][2 * dg],     A0, vb[0], vb[1]);
                mma16816(O[0][2 * dg + 1], A0, vb[2], vb[3]);
                mma16816(O[1][2 * dg],     A1, vb[0], vb[1]);
                mma16816(O[1][2 * dg + 1], A1, vb[2], vb[3]);
            }
        }

        // ---- convert + store chunk c+1 into the other buffer ----
        if (c < 7) {
            char* Kd = KsmB + ((c + 1) & 1) * 8192;
            char* Vd = VsmB + ((c + 1) & 1) * 8192;
#pragma unroll
            for (int hf = 0; hf < 2; hf++) {
                const uint32_t o0 = swz((uint32_t)(j * 128 + sub * 32 + hf * 16));
                half2 h0 = __floats2half2_rn(kR[2 * hf].x, kR[2 * hf].y);
                half2 h1 = __floats2half2_rn(kR[2 * hf].z, kR[2 * hf].w);
                half2 h2 = __floats2half2_rn(kR[2 * hf + 1].x, kR[2 * hf + 1].y);
                half2 h3 = __floats2half2_rn(kR[2 * hf + 1].z, kR[2 * hf + 1].w);
                uint4 pk = {*(uint32_t*)&h0, *(uint32_t*)&h1, *(uint32_t*)&h2, *(uint32_t*)&h3};
                *(uint4*)(Kd + o0) = pk;
                h0 = __floats2half2_rn(vR[2 * hf].x, vR[2 * hf].y);
                h1 = __floats2half2_rn(vR[2 * hf].z, vR[2 * hf].w);
                h2 = __floats2half2_rn(vR[2 * hf + 1].x, vR[2 * hf + 1].y);
                h3 = __floats2half2_rn(vR[2 * hf + 1].z, vR[2 * hf + 1].w);
                uint4 pv = {*(uint32_t*)&h0, *(uint32_t*)&h1, *(uint32_t*)&h2, *(uint32_t*)&h3};
                *(uint4*)(Vd + o0) = pv;
            }
            if (sub == 0) addv[(c + 1) & 1][j] = ad;
        }
        __syncthreads();
    }

    // ---- epilogue ----
#pragma unroll
    for (int tt = 0; tt < 2; tt++) {
        float l0 = lsum[tt][0], l1 = lsum[tt][1];
        l0 += __shfl_xor_sync(0xffffffffu, l0, 1);
        l0 += __shfl_xor_sync(0xffffffffu, l0, 2);
        l1 += __shfl_xor_sync(0xffffffffu, l1, 1);
        l1 += __shfl_xor_sync(0xffffffffu, l1, 2);
        const float inv0 = 1.0f / l0;
        const float inv1 = 1.0f / l1;
        float* o0p = out + (bhBase + qrow[tt][0]) * DIM;
        float* o1p = out + (bhBase + qrow[tt][1]) * DIM;
#pragma unroll
        for (int g = 0; g < 8; g++) {
            const int n0 = 8 * g + (lane & 3) * 2;
            float2 a = {O[tt][g][0] * inv0, O[tt][g][1] * inv0};
            float2 b = {O[tt][g][2] * inv1, O[tt][g][3] * inv1};
            *(float2*)(o0p + n0) = a;
            *(float2*)(o1p + n0) = b;
        }
    }
}

// ---------------------------------------------------------------------------
extern "C" void kernel_launch(void* const* d_in, const int* in_sizes, int n_in,
                              void* d_out, int out_size) {
    (void)in_sizes; (void)n_in; (void)out_size;
    const float* q    = (const float*)d_in[0];
    const float* k    = (const float*)d_in[1];
    const float* v    = (const float*)d_in[2];
    const float* proj = (const float*)d_in[3];
    const int*   smp  = (const int*)d_in[4];
    float* out = (float*)d_out;

    hash_kernel<<<2048, 256>>>(q, k, proj);
    sort_kernel<<<64, 128>>>();
    attn_kernel<<<dim3(32, 32), 256>>>(q, k, v, smp, out);
}

// round 11
// speedup vs baseline: 6.1360x; 1.0119x over previous
#include <cuda_runtime.h>
#include <cuda_fp16.h>
#include <cstdint>

// ---------------------------------------------------------------------------
// HyperAttention on GB300 (sm_103 baseline PTX): mma.sync m16n8k16 flash
// attention, fixed-shift softmax (log2 domain).  B=2,H=16,N=8192,D=64.
// attn CTA = 256 queries x 512 keys, 8 warps, 32 q-rows per warp.
// ---------------------------------------------------------------------------

#define BH      32
#define NSEQ    8192
#define DIM     64
#define NPROJ   7
#define NBUCK   128
#define NSEG    128
#define SEGLEN  64
#define ST      130
#define LOG32   3.4657359027997265f
#define BIGNEG  (-1e30f)
#define M_FIX   6.0f
#define LOG2E   1.4426950408889634f

__device__ unsigned char g_hash[2][BH * NSEQ];
__device__ int           g_idx[2][BH * NSEQ];   // [0]=q_idx, [1]=k_idx

// ===================== helpers =============================================
__device__ __forceinline__ uint32_t smem_u32(const void* p) {
    uint32_t a;
    asm("{ .reg .u64 t; cvta.to.shared.u64 t, %1; cvt.u32.u64 %0, t; }"
        : "=r"(a) : "l"(p));
    return a;
}
__device__ __forceinline__ uint32_t swz(uint32_t o) { return o ^ ((o >> 3) & 0x70); }

__device__ __forceinline__ float ex2f(float x) {
    float y; asm("ex2.approx.ftz.f32 %0, %1;" : "=f"(y) : "f"(x)); return y;
}
__device__ __forceinline__ void cpasync16(uint32_t d, const void* s) {
    asm volatile("cp.async.cg.shared.global [%0], [%1], 16;" :: "r"(d), "l"(s));
}
__device__ __forceinline__ void cpasync_wait() {
    asm volatile("cp.async.commit_group;\n\tcp.async.wait_group 0;" ::: "memory");
}
__device__ __forceinline__ void mma16816(float* c, const uint32_t* a,
                                         uint32_t b0, uint32_t b1) {
    asm volatile(
        "mma.sync.aligned.m16n8k16.row.col.f32.f16.f16.f32 "
        "{%0,%1,%2,%3}, {%4,%5,%6,%7}, {%8,%9}, {%0,%1,%2,%3};"
        : "+f"(c[0]), "+f"(c[1]), "+f"(c[2]), "+f"(c[3])
        : "r"(a[0]), "r"(a[1]), "r"(a[2]), "r"(a[3]), "r"(b0), "r"(b1));
}
__device__ __forceinline__ void ldsm4(uint32_t* r, uint32_t addr) {
    asm volatile("ldmatrix.sync.aligned.m8n8.x4.shared.b16 {%0,%1,%2,%3}, [%4];"
        : "=r"(r[0]), "=r"(r[1]), "=r"(r[2]), "=r"(r[3]) : "r"(addr));
}
__device__ __forceinline__ void ldsm4t(uint32_t* r, uint32_t addr) {
    asm volatile("ldmatrix.sync.aligned.m8n8.x4.trans.shared.b16 {%0,%1,%2,%3}, [%4];"
        : "=r"(r[0]), "=r"(r[1]), "=r"(r[2]), "=r"(r[3]) : "r"(addr));
}

// ---------------------------------------------------------------------------
// LSH hash: 64-row q-tile + 64-row k-tile per CTA (34KB smem -> ~5 CTAs/SM,
// cp.async staging of one CTA overlaps compute of others).
// Reduction arithmetic BIT-EXACT copy of the validated tree.
// ---------------------------------------------------------------------------
#define HROWS 64
__global__ __launch_bounds__(128)
void hash_kernel(const float* __restrict__ q,
                 const float* __restrict__ k,
                 const float* __restrict__ proj) {
    __shared__ float  pjs[NPROJ][DIM];        // pjs[r][d] = proj[d*NPROJ + r]
    __shared__ float4 buf[2][HROWS * 16];     // q-tile, k-tile (32KB)
    const int t = threadIdx.x;
    for (int i = t; i < DIM * NPROJ; i += 128)
        pjs[i % NPROJ][i / NPROJ] = proj[i];

    const float4* qs = (const float4*)q + (size_t)blockIdx.x * (HROWS * 16);
    const float4* ks = (const float4*)k + (size_t)blockIdx.x * (HROWS * 16);
    const uint32_t b0 = smem_u32(&buf[0][0]);
    const uint32_t b1 = smem_u32(&buf[1][0]);
    for (int i = t; i < HROWS * 16; i += 128) {
        const int row = i >> 4, u = i & 15;
        const uint32_t off = (uint32_t)(row * 16 + (u ^ (row & 7))) * 16u;
        cpasync16(b0 + off, qs + i);
        cpasync16(b1 + off, ks + i);
    }
    cpasync_wait();
    __syncthreads();

    const int which = t >> 6;           // 0: q rows, 1: k rows
    const int r0 = t & 63;
    const float4* mybuf = buf[which];

    float xr[DIM];
#pragma unroll
    for (int u = 0; u < 16; u++) {
        float4 f = mybuf[r0 * 16 + (u ^ (r0 & 7))];
        xr[4 * u] = f.x; xr[4 * u + 1] = f.y;
        xr[4 * u + 2] = f.z; xr[4 * u + 3] = f.w;
    }
    int code = 0;
#pragma unroll 1
    for (int r = 0; r < NPROJ; r++) {
        float a[32];
#pragma unroll
        for (int l = 0; l < 16; l++) {
            float4 p4 = *(const float4*)&pjs[r][4 * l];
            a[2 * l]     = xr[4 * l]     * p4.x + xr[4 * l + 1] * p4.y;
            a[2 * l + 1] = xr[4 * l + 2] * p4.z + xr[4 * l + 3] * p4.w;
        }
#pragma unroll
        for (int off = 16; off > 0; off >>= 1)
#pragma unroll
            for (int i = 0; i < 32; i++)
                if (i < off) a[i] += a[i + off];
        code |= (a[0] > 0.0f ? 1 : 0) << r;
    }
    g_hash[which][blockIdx.x * HROWS + r0] = (unsigned char)(code ^ (code >> 1));
}

// ---------------------------------------------------------------------------
// stable counting sort: hash bytes held in registers (no byte-LDS conflicts).
// ---------------------------------------------------------------------------
__global__ void sort_kernel() {
    __shared__ unsigned short seg[NSEG * ST];   // 33.3KB
    __shared__ int base[NBUCK];
    __shared__ int tot[NBUCK];
    const int which = blockIdx.x >> 5;
    const int bh = blockIdx.x & 31;
    const int t = threadIdx.x;                  // 0..127
    const unsigned char* hp = g_hash[which] + bh * NSEQ;
    int* op = g_idx[which] + bh * NSEQ;

    // this thread's 64 hash bytes -> 16 registers (coalesced LDG)
    uint32_t myb[16];
    {
        const uint4* p4 = (const uint4*)(hp + t * SEGLEN);
#pragma unroll
        for (int u = 0; u < 4; u++) {
            uint4 x = p4[u];
            myb[4 * u] = x.x; myb[4 * u + 1] = x.y;
            myb[4 * u + 2] = x.z; myb[4 * u + 3] = x.w;
        }
    }
    for (int i = t; i < NSEG * ST; i += NSEG) seg[i] = 0;
    __syncthreads();
    {
        unsigned short* row = seg + t * ST;
#pragma unroll 1
        for (int k2 = 0; k2 < SEGLEN; k2++) {
            int vv = (myb[k2 >> 2] >> ((k2 & 3) * 8)) & 0xff;
            row[vv]++;
        }
    }
    __syncthreads();
    {
        int run = 0;
        for (int s = 0; s < NSEG; s++) {
            int c = seg[s * ST + t];
            seg[s * ST + t] = (unsigned short)run;
            run += c;
        }
        tot[t] = run;
    }
    __syncthreads();
    if (t == 0) {
        int run = 0;
        for (int vv = 0; vv < NBUCK; vv++) { base[vv] = run; run += tot[vv]; }
    }
    __syncthreads();
    {
        unsigned short* row = seg + t * ST;
        const int b0 = t * SEGLEN;
#pragma unroll 1
        for (int k2 = 0; k2 < SEGLEN; k2++) {
            int vv = (myb[k2 >> 2] >> ((k2 & 3) * 8)) & 0xff;
            op[base[vv] + row[vv]] = b0 + k2;
            row[vv]++;
        }
    }
}

// ---------------------------------------------------------------------------
// fused attention: grid (32 qb, 32 bh), 256 threads (8 warps x 32 q-rows).
// Double-buffered K/V smem; chunk c+1 LDGs at loop top, convert+store after
// softmax (hidden behind PV MMAs), one barrier per chunk.
// ---------------------------------------------------------------------------
__global__ __launch_bounds__(256, 1)
void attn_kernel(const float* __restrict__ q, const float* __restrict__ k,
                 const float* __restrict__ v, const int* __restrict__ sampled,
                 float* __restrict__ out) {
    __shared__ __align__(128) char KsmB[2 * 8192];
    __shared__ __align__(128) char VsmB[2 * 8192];
    __shared__ float addv[2][64];

    const int tid  = threadIdx.x;
    const int w    = tid >> 5;          // 0..7
    const int lane = tid & 31;
    const int qb   = blockIdx.x;
    const int bh   = blockIdx.y;
    const size_t bhBase = (size_t)bh * NSEQ;
    const int* qidx = g_idx[0] + bhBase;
    const int* kidx = g_idx[1] + bhBase;
    const int* smp  = sampled + bh * 256;

    const uint32_t Ksm = smem_u32(KsmB);
    const uint32_t Vsm = smem_u32(VsmB);

    // ---- Q fragments: warp w owns rows [32w, 32w+32): tiles t0, t1 ----
    const int rt = 32 * w + (lane >> 2);
    int qrow[2][2];
    qrow[0][0] = qidx[qb * 256 + rt];
    qrow[0][1] = qidx[qb * 256 + rt + 8];
    qrow[1][0] = qidx[qb * 256 + rt + 16];
    qrow[1][1] = qidx[qb * 256 + rt + 24];
    const float qsc = 0.125f * LOG2E;

    uint32_t qh[2][4][4];
#pragma unroll
    for (int tt = 0; tt < 2; tt++) {
        const float* q0p = q + (bhBase + qrow[tt][0]) * DIM;
        const float* q1p = q + (bhBase + qrow[tt][1]) * DIM;
#pragma unroll
        for (int s = 0; s < 4; s++) {
            const int d = 16 * s + (lane & 3) * 2;
            float2 f00 = *(const float2*)(q0p + d);
            float2 f10 = *(const float2*)(q1p + d);
            float2 f01 = *(const float2*)(q0p + d + 8);
            float2 f11 = *(const float2*)(q1p + d + 8);
            half2 h;
            h = __floats2half2_rn(f00.x * qsc, f00.y * qsc); qh[tt][s][0] = *(uint32_t*)&h;
            h = __floats2half2_rn(f10.x * qsc, f10.y * qsc); qh[tt][s][1] = *(uint32_t*)&h;
            h = __floats2half2_rn(f01.x * qsc, f01.y * qsc); qh[tt][s][2] = *(uint32_t*)&h;
            h = __floats2half2_rn(f11.x * qsc, f11.y * qsc); qh[tt][s][3] = *(uint32_t*)&h;
        }
    }

    // ---- gather lane mapping: 4 threads per key row, 64B per tensor ----
    const int j   = tid >> 2;          // key row 0..63
    const int sub = tid & 3;           // dim quarter (16 floats)

    float O[2][8][4];
#pragma unroll
    for (int tt = 0; tt < 2; tt++)
#pragma unroll
        for (int g = 0; g < 8; g++)
#pragma unroll
            for (int e = 0; e < 4; e++) O[tt][g][e] = 0.0f;
    float lsum[2][2] = {{0.0f, 0.0f}, {0.0f, 0.0f}};

    float4 kR[4], vR[4]; float ad;

    // prologue: gather + convert chunk 0 into buffer 0
    {
        const int srow = qb * 256 + j;
        ad = -M_FIX * LOG2E;
        const int krow = kidx[srow];
        const float4* ks = (const float4*)(k + (bhBase + krow) * DIM + sub * 16);
        const float4* vs = (const float4*)(v + (bhBase + krow) * DIM + sub * 16);
#pragma unroll
        for (int u = 0; u < 4; u++) { kR[u] = ks[u]; vR[u] = vs[u]; }
#pragma unroll
        for (int hf = 0; hf < 2; hf++) {
            const uint32_t o0 = swz((uint32_t)(j * 128 + sub * 32 + hf * 16));
            half2 h0 = __floats2half2_rn(kR[2 * hf].x, kR[2 * hf].y);
            half2 h1 = __floats2half2_rn(kR[2 * hf].z, kR[2 * hf].w);
            half2 h2 = __floats2half2_rn(kR[2 * hf + 1].x, kR[2 * hf + 1].y);
            half2 h3 = __floats2half2_rn(kR[2 * hf + 1].z, kR[2 * hf + 1].w);
            uint4 pk = {*(uint32_t*)&h0, *(uint32_t*)&h1, *(uint32_t*)&h2, *(uint32_t*)&h3};
            *(uint4*)(KsmB + o0) = pk;
            h0 = __floats2half2_rn(vR[2 * hf].x, vR[2 * hf].y);
            h1 = __floats2half2_rn(vR[2 * hf].z, vR[2 * hf].w);
            h2 = __floats2half2_rn(vR[2 * hf + 1].x, vR[2 * hf + 1].y);
            h3 = __floats2half2_rn(vR[2 * hf + 1].z, vR[2 * hf + 1].w);
            uint4 pv = {*(uint32_t*)&h0, *(uint32_t*)&h1, *(uint32_t*)&h2, *(uint32_t*)&h3};
            *(uint4*)(VsmB + o0) = pv;
        }
        if (sub == 0) addv[0][j] = ad;
    }
    __syncthreads();

#pragma unroll 1
    for (int c = 0; c < 8; c++) {
        // ---- issue chunk c+1 gather LDGs early (hidden by MMAs) ----
        if (c < 7) {
            const int kk = (c + 1) * 64 + j;
            int srow;
            if (kk < 256) { srow = qb * 256 + kk; ad = -M_FIX * LOG2E; }
            else {
                int sj = smp[kk - 256];
                srow = sj;
                ad = ((sj >> 8) == qb) ? BIGNEG : ((LOG32 - M_FIX) * LOG2E);
            }
            const int krow = kidx[srow];
            const float4* ks = (const float4*)(k + (bhBase + krow) * DIM + sub * 16);
            const float4* vs = (const float4*)(v + (bhBase + krow) * DIM + sub * 16);
#pragma unroll
            for (int u = 0; u < 4; u++) { kR[u] = ks[u]; vR[u] = vs[u]; }
        }

        const uint32_t Kb = Ksm + (uint32_t)(c & 1) * 8192;
        const uint32_t Vb = Vsm + (uint32_t)(c & 1) * 8192;
        const float* av = addv[c & 1];

        // ---- S = Q.K^T + fused softmax -> P fragments (both tiles) ----
        uint32_t P01[2][8], P23[2][8];
#pragma unroll
        for (int g = 0; g < 8; g++) {
            uint32_t kb[8];
            const uint32_t key = 8u * g + (lane & 7);
            const uint32_t dv  = ((uint32_t)(lane >> 3) & 3u) * 8u;
            ldsm4(kb,     Kb + swz(key * 128 + dv * 2));
            ldsm4(kb + 4, Kb + swz(key * 128 + (32 + dv) * 2));
            const int n0 = 8 * g + (lane & 3) * 2;
            const float av0 = av[n0], av1 = av[n0 + 1];
#pragma unroll
            for (int tt = 0; tt < 2; tt++) {
                float S[4] = {0.0f, 0.0f, 0.0f, 0.0f};
#pragma unroll
                for (int s = 0; s < 4; s++)
                    mma16816(S, qh[tt][s], kb[2 * s], kb[2 * s + 1]);
                float e0 = ex2f(S[0] + av0);
                float e1 = ex2f(S[1] + av1);
                float e2 = ex2f(S[2] + av0);
                float e3 = ex2f(S[3] + av1);
                lsum[tt][0] += e0 + e1;
                lsum[tt][1] += e2 + e3;
                half2 h01 = __floats2half2_rn(e0, e1);
                half2 h23 = __floats2half2_rn(e2, e3);
                P01[tt][g] = *(uint32_t*)&h01;
                P23[tt][g] = *(uint32_t*)&h23;
            }
        }

        // ---- convert + store chunk c+1 (hidden behind the PV MMAs) ----
        if (c < 7) {
            char* Kd = KsmB + ((c + 1) & 1) * 8192;
            char* Vd = VsmB + ((c + 1) & 1) * 8192;
#pragma unroll
            for (int hf = 0; hf < 2; hf++) {
                const uint32_t o0 = swz((uint32_t)(j * 128 + sub * 32 + hf * 16));
                half2 h0 = __floats2half2_rn(kR[2 * hf].x, kR[2 * hf].y);
                half2 h1 = __floats2half2_rn(kR[2 * hf].z, kR[2 * hf].w);
                half2 h2 = __floats2half2_rn(kR[2 * hf + 1].x, kR[2 * hf + 1].y);
                half2 h3 = __floats2half2_rn(kR[2 * hf + 1].z, kR[2 * hf + 1].w);
                uint4 pk = {*(uint32_t*)&h0, *(uint32_t*)&h1, *(uint32_t*)&h2, *(uint32_t*)&h3};
                *(uint4*)(Kd + o0) = pk;
                h0 = __floats2half2_rn(vR[2 * hf].x, vR[2 * hf].y);
                h1 = __floats2half2_rn(vR[2 * hf].z, vR[2 * hf].w);
                h2 = __floats2half2_rn(vR[2 * hf + 1].x, vR[2 * hf + 1].y);
                h3 = __floats2half2_rn(vR[2 * hf + 1].z, vR[2 * hf + 1].w);
                uint4 pv = {*(uint32_t*)&h0, *(uint32_t*)&h1, *(uint32_t*)&h2, *(uint32_t*)&h3};
                *(uint4*)(Vd + o0) = pv;
            }
            if (sub == 0) addv[(c + 1) & 1][j] = ad;
        }

        // ---- O += P . V  (V fragments shared across both tiles) ----
#pragma unroll
        for (int jj = 0; jj < 4; jj++) {
            const uint32_t key = 16u * jj + ((uint32_t)lane & 15u);
            const uint32_t dof = ((uint32_t)(lane >> 4) & 1u) * 8u;
            uint32_t A0[4] = {P01[0][2 * jj], P23[0][2 * jj],
                              P01[0][2 * jj + 1], P23[0][2 * jj + 1]};
            uint32_t A1[4] = {P01[1][2 * jj], P23[1][2 * jj],
                              P01[1][2 * jj + 1], P23[1][2 * jj + 1]};
#pragma unroll
            for (int dg = 0; dg < 4; dg++) {
                uint32_t vb[4];
                ldsm4t(vb, Vb + swz(key * 128 + (16u * dg + dof) * 2));
                mma16816(O[0][2 * dg],     A0, vb[0], vb[1]);
                mma16816(O[0][2 * dg + 1], A0, vb[2], vb[3]);
                mma16816(O[1][2 * dg],     A1, vb[0], vb[1]);
                mma16816(O[1][2 * dg + 1], A1, vb[2], vb[3]);
            }
        }
        __syncthreads();
    }

    // ---- epilogue ----
#pragma unroll
    for (int tt = 0; tt < 2; tt++) {
        float l0 = lsum[tt][0], l1 = lsum[tt][1];
        l0 += __shfl_xor_sync(0xffffffffu, l0, 1);
        l0 += __shfl_xor_sync(0xffffffffu, l0, 2);
        l1 += __shfl_xor_sync(0xffffffffu, l1, 1);
        l1 += __shfl_xor_sync(0xffffffffu, l1, 2);
        const float inv0 = 1.0f / l0;
        const float inv1 = 1.0f / l1;
        float* o0p = out + (bhBase + qrow[tt][0]) * DIM;
        float* o1p = out + (bhBase + qrow[tt][1]) * DIM;
#pragma unroll
        for (int g = 0; g < 8; g++) {
            const int n0 = 8 * g + (lane & 3) * 2;
            float2 a = {O[tt][g][0] * inv0, O[tt][g][1] * inv0};
            float2 b = {O[tt][g][2] * inv1, O[tt][g][3] * inv1};
            *(float2*)(o0p + n0) = a;
            *(float2*)(o1p + n0) = b;
        }
    }
}

// ---------------------------------------------------------------------------
extern "C" void kernel_launch(void* const* d_in, const int* in_sizes, int n_in,
                              void* d_out, int out_size) {
    (void)in_sizes; (void)n_in; (void)out_size;
    const float* q    = (const float*)d_in[0];
    const float* k    = (const float*)d_in[1];
    const float* v    = (const float*)d_in[2];
    const float* proj = (const float*)d_in[3];
    const int*   smp  = (const int*)d_in[4];
    float* out = (float*)d_out;

    hash_kernel<<<(BH * NSEQ) / HROWS, 128>>>(q, k, proj);
    sort_kernel<<<64, 128>>>();
    attn_kernel<<<dim3(32, 32), 256>>>(q, k, v, smp, out);
}